// round 8
// baseline (speedup 1.0000x reference)
#include <cuda_runtime.h>
#include <cuda_bf16.h>
#include <math.h>
#include <stdint.h>

#define NNODES 50000
#define NEDGES 1600000
#define INDIM  512
#define DD1    256
#define DD2    128
#define FEPS   1e-5f
#define SCANB  ((NNODES + 255) / 256)   // 196

// ---------------- device scratch ----------------
__device__ int   g_is64;
__device__ int   g_deg[NNODES];
__device__ float g_dis[NNODES];
__device__ int   g_rowoff[NNODES + 1];
__device__ int   g_cursor[NNODES];
__device__ int   g_csr[NEDGES];
__device__ int   g_bsum[SCANB];
__device__ int   g_bpre[SCANB];
__device__ __nv_bfloat16 g_xh[(size_t)NNODES * INDIM];
__device__ __nv_bfloat16 g_xl[(size_t)NNODES * INDIM];
__device__ __nv_bfloat16 g_w1ht[DD1 * INDIM];   // [n][k]
__device__ __nv_bfloat16 g_w1lt[DD1 * INDIM];
__device__ __nv_bfloat16 g_w2ht[DD2 * DD1];
__device__ __nv_bfloat16 g_w2lt[DD2 * DD1];
__device__ float g_h1[(size_t)NNODES * DD1];
__device__ float g_agg1[(size_t)NNODES * DD1];
__device__ float g_h2[(size_t)NNODES * DD2];
__device__ float g_agg2[(size_t)NNODES * DD2];
__device__ float g_sum1[DD1], g_sq1[DD1], g_scale1[DD1], g_shift1[DD1];
__device__ float g_sum2[DD2], g_sq2[DD2], g_scale2[DD2], g_shift2[DD2];

// ---------------- helpers ----------------
__device__ __forceinline__ uint32_t smem_u32(const void* p) {
    uint32_t a;
    asm("{ .reg .u64 t; cvta.to.shared.u64 t, %1; cvt.u32.u64 %0, t; }" : "=r"(a) : "l"(p));
    return a;
}
__device__ __forceinline__ uint32_t pack_split(float a, float b, float& ra, float& rb) {
    __nv_bfloat16 ha = __float2bfloat16(a);
    __nv_bfloat16 hb = __float2bfloat16(b);
    ra = a - __bfloat162float(ha);
    rb = b - __bfloat162float(hb);
    return (uint32_t)__bfloat16_as_ushort(ha) | ((uint32_t)__bfloat16_as_ushort(hb) << 16);
}
__device__ __forceinline__ uint32_t pack_bf2(float a, float b) {
    return (uint32_t)__bfloat16_as_ushort(__float2bfloat16(a)) |
           ((uint32_t)__bfloat16_as_ushort(__float2bfloat16(b)) << 16);
}

#define LDSM_X4(f, addr) \
    asm volatile("ldmatrix.sync.aligned.m8n8.x4.shared.b16 {%0,%1,%2,%3}, [%4];" \
        : "=r"((f)[0]), "=r"((f)[1]), "=r"((f)[2]), "=r"((f)[3]) : "r"(addr))

#define MMA_BF16(c, a, b0, b1) \
    asm volatile("mma.sync.aligned.m16n8k16.row.col.f32.bf16.bf16.f32 " \
        "{%0,%1,%2,%3}, {%4,%5,%6,%7}, {%8,%9}, {%0,%1,%2,%3};" \
        : "+f"((c)[0]), "+f"((c)[1]), "+f"((c)[2]), "+f"((c)[3]) \
        : "r"((a)[0]), "r"((a)[1]), "r"((a)[2]), "r"((a)[3]), "r"(b0), "r"(b1))

#define CP16(dst, src) \
    asm volatile("cp.async.cg.shared.global [%0], [%1], 16;" :: "r"(dst), "l"(src))
#define CP_COMMIT() asm volatile("cp.async.commit_group;")
#define CP_WAIT1()  asm volatile("cp.async.wait_group 1;")
#define CP_WAIT0()  asm volatile("cp.async.wait_group 0;")

#define ASTRIDE 40   // bf16 per smem row (80B, 16B aligned, ldsm conflict-free)
#define TSZ (128 * ASTRIDE * 2)          // bytes per tile array (10240)
#define G1_SMEM (8 * TSZ)                // 2 stages x 4 arrays = 81920 B

// ---------------- init (+ edge dtype detect in block 0) ----------------
__global__ void k_init(const int* __restrict__ e) {
    int i = blockIdx.x * blockDim.x + threadIdx.x;
    if (i < NNODES) g_deg[i] = 0;
    if (i < DD1) { g_sum1[i] = 0.f; g_sq1[i] = 0.f; }
    if (i < DD2) { g_sum2[i] = 0.f; g_sq2[i] = 0.f; }
    if (i == 0) g_rowoff[NNODES] = NEDGES;
    if (blockIdx.x == 0) {
        __shared__ int any;
        if (threadIdx.x == 0) any = 0;
        __syncthreads();
        for (int j = threadIdx.x; j < 1024; j += blockDim.x)
            if (e[2 * j + 1] != 0) any = 1;
        __syncthreads();
        if (threadIdx.x == 0) g_is64 = (any ? 0 : 1);
    }
}
__device__ __forceinline__ int edge_at(const int* __restrict__ e, int idx, int is64) {
    return is64 ? e[2 * (long long)idx] : e[idx];
}

// ---------------- pre-split kernels ----------------
__global__ void k_split_x(const float* __restrict__ x) {
    size_t i = (size_t)blockIdx.x * blockDim.x + threadIdx.x;
    if (i < (size_t)NNODES * INDIM / 4) {
        float4 v = ((const float4*)x)[i];
        float r0, r1, r2, r3;
        uint32_t h01 = pack_split(v.x, v.y, r0, r1);
        uint32_t h23 = pack_split(v.z, v.w, r2, r3);
        ((uint2*)g_xh)[i] = make_uint2(h01, h23);
        ((uint2*)g_xl)[i] = make_uint2(pack_bf2(r0, r1), pack_bf2(r2, r3));
    }
}
__global__ void k_split_w1(const float* __restrict__ W1) {
    int i = blockIdx.x * blockDim.x + threadIdx.x;
    if (i < DD1 * INDIM) {
        int k = i & (INDIM - 1), n = i >> 9;
        float v = W1[k * DD1 + n];
        __nv_bfloat16 h = __float2bfloat16(v);
        g_w1ht[i] = h;
        g_w1lt[i] = __float2bfloat16(v - __bfloat162float(h));
    }
}
__global__ void k_split_w2(const float* __restrict__ W2) {
    int i = blockIdx.x * blockDim.x + threadIdx.x;
    if (i < DD2 * DD1) {
        int k = i & (DD1 - 1), n = i >> 8;
        float v = W2[k * DD2 + n];
        __nv_bfloat16 h = __float2bfloat16(v);
        g_w2ht[i] = h;
        g_w2lt[i] = __float2bfloat16(v - __bfloat162float(h));
    }
}

// ---------------- degree histogram ----------------
__global__ void k_degree(const int* __restrict__ e) {
    int i = blockIdx.x * blockDim.x + threadIdx.x;
    int is64 = g_is64;
    if (i < NEDGES) atomicAdd(&g_deg[edge_at(e, NEDGES + i, is64)], 1);
}

// ---------------- hierarchical scan ----------------
__global__ void k_scan_a() {
    __shared__ int red[256];
    int t = threadIdx.x;
    int i = blockIdx.x * 256 + t;
    int d = (i < NNODES) ? g_deg[i] : 0;
    if (i < NNODES) g_dis[i] = rsqrtf((float)(d + 1));
    red[t] = d;
    __syncthreads();
    for (int off = 128; off > 0; off >>= 1) {
        if (t < off) red[t] += red[t + off];
        __syncthreads();
    }
    if (t == 0) g_bsum[blockIdx.x] = red[0];
}
__global__ void k_scan_b() {
    __shared__ int s[256];
    int t = threadIdx.x;
    int v = (t < SCANB) ? g_bsum[t] : 0;
    s[t] = v;
    __syncthreads();
    for (int off = 1; off < 256; off <<= 1) {
        int u = (t >= off) ? s[t - off] : 0;
        __syncthreads();
        s[t] += u;
        __syncthreads();
    }
    if (t < SCANB) g_bpre[t] = s[t] - v;
}
__global__ void k_scan_c() {
    __shared__ int s[256];
    int t = threadIdx.x;
    int i = blockIdx.x * 256 + t;
    int d = (i < NNODES) ? g_deg[i] : 0;
    s[t] = d;
    __syncthreads();
    for (int off = 1; off < 256; off <<= 1) {
        int u = (t >= off) ? s[t - off] : 0;
        __syncthreads();
        s[t] += u;
        __syncthreads();
    }
    if (i < NNODES) {
        int excl = s[t] - d + g_bpre[blockIdx.x];
        g_rowoff[i] = excl;
        g_cursor[i] = excl;
    }
}

// ---------------- CSR bucket scatter ----------------
__global__ void k_scatter(const int* __restrict__ e) {
    int i = blockIdx.x * blockDim.x + threadIdx.x;
    int is64 = g_is64;
    if (i < NEDGES) {
        int s = edge_at(e, i, is64);
        int d = edge_at(e, NEDGES + i, is64);
        g_csr[atomicAdd(&g_cursor[d], 1)] = s;
    }
}

// ---------------- shared mma compute/epilogue ----------------
__device__ __forceinline__ void compute_k32(uint32_t bAh, uint32_t bAl, uint32_t bBh,
                                            uint32_t bBl, float (&acc)[2][8][4],
                                            int wm, int wn, int l) {
    int a_r = (l & 7) + ((l >> 3) & 1) * 8;
    int a_c = ((l >> 4) & 1) * 8;
    int b_n = (l & 7) + ((l >> 4) & 1) * 8;
    int b_k = ((l >> 3) & 1) * 8;
#pragma unroll
    for (int kk = 0; kk < 32; kk += 16) {
        uint32_t ah[2][4], al[2][4];
#pragma unroll
        for (int mi = 0; mi < 2; mi++) {
            int r = wm * 32 + mi * 16 + a_r;
            uint32_t off = (uint32_t)(r * (ASTRIDE * 2) + (kk + a_c) * 2);
            LDSM_X4(ah[mi], bAh + off);
            LDSM_X4(al[mi], bAl + off);
        }
#pragma unroll
        for (int ng = 0; ng < 4; ng++) {
            uint32_t bh[4], bl[4];
            int nr = wn * 64 + ng * 16 + b_n;
            uint32_t off = (uint32_t)(nr * (ASTRIDE * 2) + (kk + b_k) * 2);
            LDSM_X4(bh, bBh + off);
            LDSM_X4(bl, bBl + off);
#pragma unroll
            for (int mi = 0; mi < 2; mi++) {
                MMA_BF16(acc[mi][ng * 2 + 0], ah[mi], bh[0], bh[1]);
                MMA_BF16(acc[mi][ng * 2 + 0], ah[mi], bl[0], bl[1]);
                MMA_BF16(acc[mi][ng * 2 + 0], al[mi], bh[0], bh[1]);
                MMA_BF16(acc[mi][ng * 2 + 1], ah[mi], bh[2], bh[3]);
                MMA_BF16(acc[mi][ng * 2 + 1], ah[mi], bl[2], bl[3]);
                MMA_BF16(acc[mi][ng * 2 + 1], al[mi], bh[2], bh[3]);
            }
        }
    }
}
__device__ __forceinline__ void epilogue(float* __restrict__ C, int NT, int m0, int n0,
                                         float (&acc)[2][8][4], int wm, int wn, int l) {
#pragma unroll
    for (int mi = 0; mi < 2; mi++) {
#pragma unroll
        for (int ni = 0; ni < 8; ni++) {
            int r = m0 + wm * 32 + mi * 16 + (l >> 2);
            int cc = n0 + wn * 64 + ni * 8 + (l & 3) * 2;
            if (r < NNODES)
                *(float2*)(C + (size_t)r * NT + cc) = make_float2(acc[mi][ni][0], acc[mi][ni][1]);
            if (r + 8 < NNODES)
                *(float2*)(C + (size_t)(r + 8) * NT + cc) = make_float2(acc[mi][ni][2], acc[mi][ni][3]);
        }
    }
}

// ---------------- GEMM1: cp.async double-buffered, pre-split bf16 ----------------
__global__ __launch_bounds__(256) void k_gemm1() {
    extern __shared__ __align__(16) char sm[];
    int tid = threadIdx.x, wid = tid >> 5, l = tid & 31;
    int m0 = blockIdx.y * 128, n0 = blockIdx.x * 128;
    int wm = wid & 3, wn = wid >> 2;

    int row = tid >> 1, half = (tid & 1) * 16;   // 16 bf16 per thread
    int gr = m0 + row; if (gr > NNODES - 1) gr = NNODES - 1;
    const __nv_bfloat16* Ah = g_xh + (size_t)gr * INDIM + half;
    const __nv_bfloat16* Al = g_xl + (size_t)gr * INDIM + half;
    const __nv_bfloat16* Bh = g_w1ht + (size_t)(n0 + row) * INDIM + half;
    const __nv_bfloat16* Bl = g_w1lt + (size_t)(n0 + row) * INDIM + half;

    uint32_t base = smem_u32(sm);
    uint32_t soff = (uint32_t)(row * ASTRIDE + half) * 2;   // byte offset in tile

    float acc[2][8][4];
#pragma unroll
    for (int a = 0; a < 2; a++)
#pragma unroll
        for (int b = 0; b < 8; b++)
#pragma unroll
            for (int c = 0; c < 4; c++) acc[a][b][c] = 0.f;

    // stage(buf, k0): 8 x 16B cp.async
#define G1_STAGE(buf, k0) do { \
        uint32_t s0 = base + (buf) * (4 * TSZ) + soff; \
        CP16(s0 + 0 * TSZ,      Ah + (k0));      CP16(s0 + 0 * TSZ + 16, Ah + (k0) + 8); \
        CP16(s0 + 1 * TSZ,      Al + (k0));      CP16(s0 + 1 * TSZ + 16, Al + (k0) + 8); \
        CP16(s0 + 2 * TSZ,      Bh + (k0));      CP16(s0 + 2 * TSZ + 16, Bh + (k0) + 8); \
        CP16(s0 + 3 * TSZ,      Bl + (k0));      CP16(s0 + 3 * TSZ + 16, Bl + (k0) + 8); \
        CP_COMMIT(); \
    } while (0)

    G1_STAGE(0, 0);
    const int NIT = INDIM / 32;   // 16
    for (int it = 0; it < NIT; it++) {
        int cur = it & 1;
        if (it + 1 < NIT) G1_STAGE(cur ^ 1, (it + 1) * 32);
        if (it + 1 < NIT) CP_WAIT1(); else CP_WAIT0();
        __syncthreads();
        uint32_t tb = base + cur * (4 * TSZ);
        compute_k32(tb, tb + TSZ, tb + 2 * TSZ, tb + 3 * TSZ, acc, wm, wn, l);
        __syncthreads();
    }
#undef G1_STAGE
    epilogue(g_h1, DD1, m0, n0, acc, wm, wn, l);
}

// ---------------- GEMM2: fp32 A (agg1, BN1+ReLU fused+split) x pre-split B ----------------
__global__ __launch_bounds__(256) void k_gemm2() {
    __shared__ __align__(16) __nv_bfloat16 As_h[128 * ASTRIDE];
    __shared__ __align__(16) __nv_bfloat16 As_l[128 * ASTRIDE];
    __shared__ __align__(16) __nv_bfloat16 Bs_h[128 * ASTRIDE];
    __shared__ __align__(16) __nv_bfloat16 Bs_l[128 * ASTRIDE];
    int tid = threadIdx.x, wid = tid >> 5, l = tid & 31;
    int m0 = blockIdx.y * 128, n0 = 0;
    int wm = wid & 3, wn = wid >> 2;
    uint32_t bAh = smem_u32(As_h), bAl = smem_u32(As_l);
    uint32_t bBh = smem_u32(Bs_h), bBl = smem_u32(Bs_l);

    int row = tid >> 1;
    int half = (tid & 1) * 16;
    int gr = m0 + row; if (gr > NNODES - 1) gr = NNODES - 1;
    const float* Arow = g_agg1 + (size_t)gr * DD1;
    const __nv_bfloat16* Bh = g_w2ht + (size_t)(n0 + row) * DD1 + half;
    const __nv_bfloat16* Bl = g_w2lt + (size_t)(n0 + row) * DD1 + half;
    int soff = row * ASTRIDE + half;

    float acc[2][8][4];
#pragma unroll
    for (int a = 0; a < 2; a++)
#pragma unroll
        for (int b = 0; b < 8; b++)
#pragma unroll
            for (int c = 0; c < 4; c++) acc[a][b][c] = 0.f;

    for (int k0 = 0; k0 < DD1; k0 += 32) {
#pragma unroll
        for (int q = 0; q < 4; q++) {
            int c = half + q * 4;
            float4 v = *(const float4*)(Arow + k0 + c);
            int cc = k0 + c;
            v.x = fmaxf(fmaf(v.x, g_scale1[cc + 0], g_shift1[cc + 0]), 0.f);
            v.y = fmaxf(fmaf(v.y, g_scale1[cc + 1], g_shift1[cc + 1]), 0.f);
            v.z = fmaxf(fmaf(v.z, g_scale1[cc + 2], g_shift1[cc + 2]), 0.f);
            v.w = fmaxf(fmaf(v.w, g_scale1[cc + 3], g_shift1[cc + 3]), 0.f);
            float r0, r1, r2, r3;
            uint32_t h01 = pack_split(v.x, v.y, r0, r1);
            uint32_t h23 = pack_split(v.z, v.w, r2, r3);
            int off = row * ASTRIDE + c;
            *(uint2*)(As_h + off) = make_uint2(h01, h23);
            *(uint2*)(As_l + off) = make_uint2(pack_bf2(r0, r1), pack_bf2(r2, r3));
        }
        *(uint4*)(Bs_h + soff)     = *(const uint4*)(Bh + k0);
        *(uint4*)(Bs_h + soff + 8) = *(const uint4*)(Bh + k0 + 8);
        *(uint4*)(Bs_l + soff)     = *(const uint4*)(Bl + k0);
        *(uint4*)(Bs_l + soff + 8) = *(const uint4*)(Bl + k0 + 8);
        __syncthreads();
        compute_k32(bAh, bAl, bBh, bBl, acc, wm, wn, l);
        __syncthreads();
    }
    epilogue(g_h2, DD2, m0, n0, acc, wm, wn, l);
}

// ---------------- warp-per-node gather aggregation + fused BN stats ----------------
// grid: exactly NNODES/8 blocks of 256 threads (50000 % 8 == 0).
template <int DIM>
__global__ void k_aggw(const float* __restrict__ H, float* __restrict__ O,
                       float* __restrict__ gsum, float* __restrict__ gsq) {
    __shared__ float ssum[DIM], ssq[DIM];
    int tid = threadIdx.x;
    int warp = (blockIdx.x * blockDim.x + tid) >> 5;
    int lane = tid & 31;
    for (int c = tid; c < DIM; c += 256) { ssum[c] = 0.f; ssq[c] = 0.f; }
    __syncthreads();

    constexpr int V = DIM / 128;
    float4 acc[V];
    int d = warp;
    if (d < NNODES) {
        float dd = g_dis[d];
        const float4* Hd = (const float4*)(H + (size_t)d * DIM);
#pragma unroll
        for (int v = 0; v < V; v++) {
            float4 x = Hd[lane + 32 * v];
            acc[v] = make_float4(dd * x.x, dd * x.y, dd * x.z, dd * x.w);
        }
        int beg = g_rowoff[d], end = g_rowoff[d + 1];
        for (int base = beg; base < end; base += 32) {
            int cnt = min(end - base, 32);
            int s = 0; float w = 0.f;
            if (lane < cnt) {
                s = g_csr[base + lane];
                w = g_dis[s];
            }
            for (int j = 0; j < cnt; j++) {
                int sj = __shfl_sync(0xffffffffu, s, j);
                float wj = __shfl_sync(0xffffffffu, w, j);
                const float4* R = (const float4*)(H + (size_t)sj * DIM);
#pragma unroll
                for (int v = 0; v < V; v++) {
                    float4 x = R[lane + 32 * v];
                    acc[v].x = fmaf(wj, x.x, acc[v].x);
                    acc[v].y = fmaf(wj, x.y, acc[v].y);
                    acc[v].z = fmaf(wj, x.z, acc[v].z);
                    acc[v].w = fmaf(wj, x.w, acc[v].w);
                }
            }
        }
        float4* Od = (float4*)(O + (size_t)d * DIM);
#pragma unroll
        for (int v = 0; v < V; v++) {
            float4 r = make_float4(acc[v].x * dd, acc[v].y * dd, acc[v].z * dd, acc[v].w * dd);
            Od[lane + 32 * v] = r;
            int c = (lane + 32 * v) * 4;
            atomicAdd(&ssum[c + 0], r.x);  atomicAdd(&ssq[c + 0], r.x * r.x);
            atomicAdd(&ssum[c + 1], r.y);  atomicAdd(&ssq[c + 1], r.y * r.y);
            atomicAdd(&ssum[c + 2], r.z);  atomicAdd(&ssq[c + 2], r.z * r.z);
            atomicAdd(&ssum[c + 3], r.w);  atomicAdd(&ssq[c + 3], r.w * r.w);
        }
    }
    __syncthreads();
    for (int c = tid; c < DIM; c += 256) {
        atomicAdd(&gsum[c], ssum[c]);
        atomicAdd(&gsq[c], ssq[c]);
    }
}

// ---------------- BN finalize ----------------
template <int DIM>
__device__ __forceinline__ void finalize_impl(const float* __restrict__ sum,
                                              const float* __restrict__ sq,
                                              const float* __restrict__ gamma,
                                              const float* __restrict__ beta,
                                              float* __restrict__ scale,
                                              float* __restrict__ shift) {
    int t = threadIdx.x;
    float mean = sum[t] * (1.f / NNODES);
    float var = fmaxf(sq[t] * (1.f / NNODES) - mean * mean, 0.f);
    float sc = rsqrtf(var + FEPS) * gamma[t];
    scale[t] = sc;
    shift[t] = beta[t] - mean * sc;
}
__global__ void k_finalize1(const float* g, const float* b) {
    finalize_impl<DD1>(g_sum1, g_sq1, g, b, g_scale1, g_shift1);
}
__global__ void k_finalize2(const float* g, const float* b) {
    finalize_impl<DD2>(g_sum2, g_sq2, g, b, g_scale2, g_shift2);
}

// ---------------- final BN2 apply -> d_out ----------------
__global__ void k_apply(float* __restrict__ out) {
    int i = blockIdx.x * blockDim.x + threadIdx.x;
    if (i < NNODES * DD2) {
        int c = i & (DD2 - 1);
        out[i] = g_agg2[i] * g_scale2[c] + g_shift2[c];
    }
}

// ---------------- launch ----------------
extern "C" void kernel_launch(void* const* d_in, const int* in_sizes, int n_in,
                              void* d_out, int out_size) {
    const float* x      = (const float*)d_in[0];
    const int*   e      = (const int*)d_in[1];
    const float* W1     = (const float*)d_in[2];
    const float* gamma1 = (const float*)d_in[4];
    const float* beta1  = (const float*)d_in[5];
    const float* W2     = (const float*)d_in[6];
    const float* gamma2 = (const float*)d_in[8];
    const float* beta2  = (const float*)d_in[9];
    float* out = (float*)d_out;

    void *p_h1, *p_agg1, *p_h2, *p_agg2, *p_s1, *p_q1, *p_s2, *p_q2;
    cudaGetSymbolAddress(&p_h1, g_h1);
    cudaGetSymbolAddress(&p_agg1, g_agg1);
    cudaGetSymbolAddress(&p_h2, g_h2);
    cudaGetSymbolAddress(&p_agg2, g_agg2);
    cudaGetSymbolAddress(&p_s1, g_sum1);
    cudaGetSymbolAddress(&p_q1, g_sq1);
    cudaGetSymbolAddress(&p_s2, g_sum2);
    cudaGetSymbolAddress(&p_q2, g_sq2);

    cudaFuncSetAttribute(k_gemm1, cudaFuncAttributeMaxDynamicSharedMemorySize, G1_SMEM);

    const int EG = (NEDGES + 255) / 256;
    const int MB = (NNODES + 127) / 128;       // 391
    const int AGG_G = NNODES / 8;              // 6250 (warp-per-node, exact)

    k_init<<<(NNODES + 255) / 256, 256>>>(e);
    k_split_x<<<(NNODES * INDIM / 4 + 255) / 256, 256>>>(x);
    k_split_w1<<<(DD1 * INDIM + 255) / 256, 256>>>(W1);
    k_split_w2<<<(DD2 * DD1 + 255) / 256, 256>>>(W2);

    k_degree<<<EG, 256>>>(e);
    k_scan_a<<<SCANB, 256>>>();
    k_scan_b<<<1, 256>>>();
    k_scan_c<<<SCANB, 256>>>();
    k_scatter<<<EG, 256>>>(e);

    k_gemm1<<<dim3(2, MB), 256, G1_SMEM>>>();
    k_aggw<DD1><<<AGG_G, 256>>>((const float*)p_h1, (float*)p_agg1, (float*)p_s1, (float*)p_q1);
    k_finalize1<<<1, DD1>>>(gamma1, beta1);

    k_gemm2<<<dim3(1, MB), 256>>>();
    k_aggw<DD2><<<AGG_G, 256>>>((const float*)p_h2, (float*)p_agg2, (float*)p_s2, (float*)p_q2);
    k_finalize2<<<1, DD2>>>(gamma2, beta2);

    k_apply<<<(NNODES * DD2 + 255) / 256, 256>>>(out);
}

// round 10
// speedup vs baseline: 1.0612x; 1.0612x over previous
#include <cuda_runtime.h>
#include <cuda_bf16.h>
#include <math.h>
#include <stdint.h>

#define NNODES 50000
#define NEDGES 1600000
#define INDIM  512
#define DD1    256
#define DD2    128
#define FEPS   1e-5f
#define SCANB  ((NNODES + 255) / 256)   // 196

// ---------------- device scratch ----------------
__device__ int   g_is64;
__device__ int   g_deg[NNODES];
__device__ float g_dis[NNODES];
__device__ int   g_rowoff[NNODES + 1];
__device__ int   g_cursor[NNODES];
__device__ int   g_csr[NEDGES];
__device__ int   g_bsum[SCANB];
__device__ int   g_bpre[SCANB];
__device__ __nv_bfloat16 g_xh[(size_t)NNODES * INDIM];
__device__ __nv_bfloat16 g_xl[(size_t)NNODES * INDIM];
__device__ __nv_bfloat16 g_w1ht[DD1 * INDIM];   // [n][k]
__device__ __nv_bfloat16 g_w1lt[DD1 * INDIM];
__device__ __nv_bfloat16 g_w2ht[DD2 * DD1];
__device__ __nv_bfloat16 g_w2lt[DD2 * DD1];
__device__ float g_h1[(size_t)NNODES * DD1];
__device__ float g_agg1[(size_t)NNODES * DD1];
__device__ float g_h2[(size_t)NNODES * DD2];
__device__ float g_agg2[(size_t)NNODES * DD2];
__device__ float g_sum1[DD1], g_sq1[DD1], g_scale1[DD1], g_shift1[DD1];
__device__ float g_sum2[DD2], g_sq2[DD2], g_scale2[DD2], g_shift2[DD2];

// ---------------- helpers ----------------
__device__ __forceinline__ uint32_t smem_u32(const void* p) {
    uint32_t a;
    asm("{ .reg .u64 t; cvta.to.shared.u64 t, %1; cvt.u32.u64 %0, t; }" : "=r"(a) : "l"(p));
    return a;
}
__device__ __forceinline__ uint32_t pack_split(float a, float b, float& ra, float& rb) {
    __nv_bfloat16 ha = __float2bfloat16(a);
    __nv_bfloat16 hb = __float2bfloat16(b);
    ra = a - __bfloat162float(ha);
    rb = b - __bfloat162float(hb);
    return (uint32_t)__bfloat16_as_ushort(ha) | ((uint32_t)__bfloat16_as_ushort(hb) << 16);
}
__device__ __forceinline__ uint32_t pack_bf2(float a, float b) {
    return (uint32_t)__bfloat16_as_ushort(__float2bfloat16(a)) |
           ((uint32_t)__bfloat16_as_ushort(__float2bfloat16(b)) << 16);
}

#define LDSM_X4(f, addr) \
    asm volatile("ldmatrix.sync.aligned.m8n8.x4.shared.b16 {%0,%1,%2,%3}, [%4];" \
        : "=r"((f)[0]), "=r"((f)[1]), "=r"((f)[2]), "=r"((f)[3]) : "r"(addr))

#define MMA_BF16(c, a, b0, b1) \
    asm volatile("mma.sync.aligned.m16n8k16.row.col.f32.bf16.bf16.f32 " \
        "{%0,%1,%2,%3}, {%4,%5,%6,%7}, {%8,%9}, {%0,%1,%2,%3};" \
        : "+f"((c)[0]), "+f"((c)[1]), "+f"((c)[2]), "+f"((c)[3]) \
        : "r"((a)[0]), "r"((a)[1]), "r"((a)[2]), "r"((a)[3]), "r"(b0), "r"(b1))

#define CP16(dst, src) \
    asm volatile("cp.async.cg.shared.global [%0], [%1], 16;" :: "r"(dst), "l"(src))
#define CP_COMMIT() asm volatile("cp.async.commit_group;")
#define CP_WAIT1()  asm volatile("cp.async.wait_group 1;")
#define CP_WAIT0()  asm volatile("cp.async.wait_group 0;")

#define ASTRIDE 40   // bf16 per smem row (80B, 16B aligned, ldsm conflict-free)
#define TSZ (128 * ASTRIDE * 2)          // bytes per tile array (10240)
#define G1_SMEM (8 * TSZ)                // 2 stages x 4 arrays = 81920 B

// ---------------- init (+ edge dtype detect in block 0) ----------------
__global__ void k_init(const int* __restrict__ e) {
    int i = blockIdx.x * blockDim.x + threadIdx.x;
    if (i < NNODES) g_deg[i] = 0;
    if (i < DD1) { g_sum1[i] = 0.f; g_sq1[i] = 0.f; }
    if (i < DD2) { g_sum2[i] = 0.f; g_sq2[i] = 0.f; }
    if (i == 0) g_rowoff[NNODES] = NEDGES;
    if (blockIdx.x == 0) {
        __shared__ int any;
        if (threadIdx.x == 0) any = 0;
        __syncthreads();
        for (int j = threadIdx.x; j < 1024; j += blockDim.x)
            if (e[2 * j + 1] != 0) any = 1;
        __syncthreads();
        if (threadIdx.x == 0) g_is64 = (any ? 0 : 1);
    }
}
__device__ __forceinline__ int edge_at(const int* __restrict__ e, int idx, int is64) {
    return is64 ? e[2 * (long long)idx] : e[idx];
}

// ---------------- pre-split kernels ----------------
__global__ void k_split_x(const float* __restrict__ x) {
    size_t i = (size_t)blockIdx.x * blockDim.x + threadIdx.x;
    if (i < (size_t)NNODES * INDIM / 4) {
        float4 v = ((const float4*)x)[i];
        float r0, r1, r2, r3;
        uint32_t h01 = pack_split(v.x, v.y, r0, r1);
        uint32_t h23 = pack_split(v.z, v.w, r2, r3);
        ((uint2*)g_xh)[i] = make_uint2(h01, h23);
        ((uint2*)g_xl)[i] = make_uint2(pack_bf2(r0, r1), pack_bf2(r2, r3));
    }
}
__global__ void k_split_w1(const float* __restrict__ W1) {
    int i = blockIdx.x * blockDim.x + threadIdx.x;
    if (i < DD1 * INDIM) {
        int k = i & (INDIM - 1), n = i >> 9;
        float v = W1[k * DD1 + n];
        __nv_bfloat16 h = __float2bfloat16(v);
        g_w1ht[i] = h;
        g_w1lt[i] = __float2bfloat16(v - __bfloat162float(h));
    }
}
__global__ void k_split_w2(const float* __restrict__ W2) {
    int i = blockIdx.x * blockDim.x + threadIdx.x;
    if (i < DD2 * DD1) {
        int k = i & (DD1 - 1), n = i >> 8;
        float v = W2[k * DD2 + n];
        __nv_bfloat16 h = __float2bfloat16(v);
        g_w2ht[i] = h;
        g_w2lt[i] = __float2bfloat16(v - __bfloat162float(h));
    }
}

// ---------------- degree histogram ----------------
__global__ void k_degree(const int* __restrict__ e) {
    int i = blockIdx.x * blockDim.x + threadIdx.x;
    int is64 = g_is64;
    if (i < NEDGES) atomicAdd(&g_deg[edge_at(e, NEDGES + i, is64)], 1);
}

// ---------------- hierarchical scan ----------------
__global__ void k_scan_a() {
    __shared__ int red[256];
    int t = threadIdx.x;
    int i = blockIdx.x * 256 + t;
    int d = (i < NNODES) ? g_deg[i] : 0;
    if (i < NNODES) g_dis[i] = rsqrtf((float)(d + 1));
    red[t] = d;
    __syncthreads();
    for (int off = 128; off > 0; off >>= 1) {
        if (t < off) red[t] += red[t + off];
        __syncthreads();
    }
    if (t == 0) g_bsum[blockIdx.x] = red[0];
}
__global__ void k_scan_b() {
    __shared__ int s[256];
    int t = threadIdx.x;
    int v = (t < SCANB) ? g_bsum[t] : 0;
    s[t] = v;
    __syncthreads();
    for (int off = 1; off < 256; off <<= 1) {
        int u = (t >= off) ? s[t - off] : 0;
        __syncthreads();
        s[t] += u;
        __syncthreads();
    }
    if (t < SCANB) g_bpre[t] = s[t] - v;
}
__global__ void k_scan_c() {
    __shared__ int s[256];
    int t = threadIdx.x;
    int i = blockIdx.x * 256 + t;
    int d = (i < NNODES) ? g_deg[i] : 0;
    s[t] = d;
    __syncthreads();
    for (int off = 1; off < 256; off <<= 1) {
        int u = (t >= off) ? s[t - off] : 0;
        __syncthreads();
        s[t] += u;
        __syncthreads();
    }
    if (i < NNODES) {
        int excl = s[t] - d + g_bpre[blockIdx.x];
        g_rowoff[i] = excl;
        g_cursor[i] = excl;
    }
}

// ---------------- CSR bucket scatter ----------------
__global__ void k_scatter(const int* __restrict__ e) {
    int i = blockIdx.x * blockDim.x + threadIdx.x;
    int is64 = g_is64;
    if (i < NEDGES) {
        int s = edge_at(e, i, is64);
        int d = edge_at(e, NEDGES + i, is64);
        g_csr[atomicAdd(&g_cursor[d], 1)] = s;
    }
}

// ---------------- shared mma compute/epilogue ----------------
__device__ __forceinline__ void compute_k32(uint32_t bAh, uint32_t bAl, uint32_t bBh,
                                            uint32_t bBl, float (&acc)[2][8][4],
                                            int wm, int wn, int l) {
    int a_r = (l & 7) + ((l >> 3) & 1) * 8;
    int a_c = ((l >> 4) & 1) * 8;
    int b_n = (l & 7) + ((l >> 4) & 1) * 8;
    int b_k = ((l >> 3) & 1) * 8;
#pragma unroll
    for (int kk = 0; kk < 32; kk += 16) {
        uint32_t ah[2][4], al[2][4];
#pragma unroll
        for (int mi = 0; mi < 2; mi++) {
            int r = wm * 32 + mi * 16 + a_r;
            uint32_t off = (uint32_t)(r * (ASTRIDE * 2) + (kk + a_c) * 2);
            LDSM_X4(ah[mi], bAh + off);
            LDSM_X4(al[mi], bAl + off);
        }
#pragma unroll
        for (int ng = 0; ng < 4; ng++) {
            uint32_t bh[4], bl[4];
            int nr = wn * 64 + ng * 16 + b_n;
            uint32_t off = (uint32_t)(nr * (ASTRIDE * 2) + (kk + b_k) * 2);
            LDSM_X4(bh, bBh + off);
            LDSM_X4(bl, bBl + off);
#pragma unroll
            for (int mi = 0; mi < 2; mi++) {
                MMA_BF16(acc[mi][ng * 2 + 0], ah[mi], bh[0], bh[1]);
                MMA_BF16(acc[mi][ng * 2 + 0], ah[mi], bl[0], bl[1]);
                MMA_BF16(acc[mi][ng * 2 + 0], al[mi], bh[0], bh[1]);
                MMA_BF16(acc[mi][ng * 2 + 1], ah[mi], bh[2], bh[3]);
                MMA_BF16(acc[mi][ng * 2 + 1], ah[mi], bl[2], bl[3]);
                MMA_BF16(acc[mi][ng * 2 + 1], al[mi], bh[2], bh[3]);
            }
        }
    }
}
__device__ __forceinline__ void epilogue(float* __restrict__ C, int NT, int m0, int n0,
                                         float (&acc)[2][8][4], int wm, int wn, int l) {
#pragma unroll
    for (int mi = 0; mi < 2; mi++) {
#pragma unroll
        for (int ni = 0; ni < 8; ni++) {
            int r = m0 + wm * 32 + mi * 16 + (l >> 2);
            int cc = n0 + wn * 64 + ni * 8 + (l & 3) * 2;
            if (r < NNODES)
                *(float2*)(C + (size_t)r * NT + cc) = make_float2(acc[mi][ni][0], acc[mi][ni][1]);
            if (r + 8 < NNODES)
                *(float2*)(C + (size_t)(r + 8) * NT + cc) = make_float2(acc[mi][ni][2], acc[mi][ni][3]);
        }
    }
}

// ---------------- GEMM1: cp.async double-buffered, pre-split bf16 ----------------
__global__ __launch_bounds__(256) void k_gemm1() {
    extern __shared__ __align__(16) char sm[];
    int tid = threadIdx.x, wid = tid >> 5, l = tid & 31;
    int m0 = blockIdx.y * 128, n0 = blockIdx.x * 128;
    int wm = wid & 3, wn = wid >> 2;

    int row = tid >> 1, half = (tid & 1) * 16;   // 16 bf16 per thread
    int gr = m0 + row; if (gr > NNODES - 1) gr = NNODES - 1;
    const __nv_bfloat16* Ah = g_xh + (size_t)gr * INDIM + half;
    const __nv_bfloat16* Al = g_xl + (size_t)gr * INDIM + half;
    const __nv_bfloat16* Bh = g_w1ht + (size_t)(n0 + row) * INDIM + half;
    const __nv_bfloat16* Bl = g_w1lt + (size_t)(n0 + row) * INDIM + half;

    uint32_t base = smem_u32(sm);
    uint32_t soff = (uint32_t)(row * ASTRIDE + half) * 2;   // byte offset in tile

    float acc[2][8][4];
#pragma unroll
    for (int a = 0; a < 2; a++)
#pragma unroll
        for (int b = 0; b < 8; b++)
#pragma unroll
            for (int c = 0; c < 4; c++) acc[a][b][c] = 0.f;

#define G1_STAGE(buf, k0) do { \
        uint32_t s0 = base + (buf) * (4 * TSZ) + soff; \
        CP16(s0 + 0 * TSZ,      Ah + (k0));      CP16(s0 + 0 * TSZ + 16, Ah + (k0) + 8); \
        CP16(s0 + 1 * TSZ,      Al + (k0));      CP16(s0 + 1 * TSZ + 16, Al + (k0) + 8); \
        CP16(s0 + 2 * TSZ,      Bh + (k0));      CP16(s0 + 2 * TSZ + 16, Bh + (k0) + 8); \
        CP16(s0 + 3 * TSZ,      Bl + (k0));      CP16(s0 + 3 * TSZ + 16, Bl + (k0) + 8); \
        CP_COMMIT(); \
    } while (0)

    G1_STAGE(0, 0);
    const int NIT = INDIM / 32;   // 16
    for (int it = 0; it < NIT; it++) {
        int cur = it & 1;
        if (it + 1 < NIT) G1_STAGE(cur ^ 1, (it + 1) * 32);
        if (it + 1 < NIT) CP_WAIT1(); else CP_WAIT0();
        __syncthreads();
        uint32_t tb = base + cur * (4 * TSZ);
        compute_k32(tb, tb + TSZ, tb + 2 * TSZ, tb + 3 * TSZ, acc, wm, wn, l);
        __syncthreads();
    }
#undef G1_STAGE
    epilogue(g_h1, DD1, m0, n0, acc, wm, wn, l);
}

// ---------------- GEMM2: fp32 A (agg1, BN1+ReLU fused+split) x pre-split B ----------------
__global__ __launch_bounds__(256) void k_gemm2() {
    __shared__ __align__(16) __nv_bfloat16 As_h[128 * ASTRIDE];
    __shared__ __align__(16) __nv_bfloat16 As_l[128 * ASTRIDE];
    __shared__ __align__(16) __nv_bfloat16 Bs_h[128 * ASTRIDE];
    __shared__ __align__(16) __nv_bfloat16 Bs_l[128 * ASTRIDE];
    int tid = threadIdx.x, wid = tid >> 5, l = tid & 31;
    int m0 = blockIdx.y * 128, n0 = 0;
    int wm = wid & 3, wn = wid >> 2;
    uint32_t bAh = smem_u32(As_h), bAl = smem_u32(As_l);
    uint32_t bBh = smem_u32(Bs_h), bBl = smem_u32(Bs_l);

    int row = tid >> 1;
    int half = (tid & 1) * 16;
    int gr = m0 + row; if (gr > NNODES - 1) gr = NNODES - 1;
    const float* Arow = g_agg1 + (size_t)gr * DD1;
    const __nv_bfloat16* Bh = g_w2ht + (size_t)(n0 + row) * DD1 + half;
    const __nv_bfloat16* Bl = g_w2lt + (size_t)(n0 + row) * DD1 + half;
    int soff = row * ASTRIDE + half;

    float acc[2][8][4];
#pragma unroll
    for (int a = 0; a < 2; a++)
#pragma unroll
        for (int b = 0; b < 8; b++)
#pragma unroll
            for (int c = 0; c < 4; c++) acc[a][b][c] = 0.f;

    for (int k0 = 0; k0 < DD1; k0 += 32) {
#pragma unroll
        for (int q = 0; q < 4; q++) {
            int c = half + q * 4;
            float4 v = *(const float4*)(Arow + k0 + c);
            int cc = k0 + c;
            v.x = fmaxf(fmaf(v.x, g_scale1[cc + 0], g_shift1[cc + 0]), 0.f);
            v.y = fmaxf(fmaf(v.y, g_scale1[cc + 1], g_shift1[cc + 1]), 0.f);
            v.z = fmaxf(fmaf(v.z, g_scale1[cc + 2], g_shift1[cc + 2]), 0.f);
            v.w = fmaxf(fmaf(v.w, g_scale1[cc + 3], g_shift1[cc + 3]), 0.f);
            float r0, r1, r2, r3;
            uint32_t h01 = pack_split(v.x, v.y, r0, r1);
            uint32_t h23 = pack_split(v.z, v.w, r2, r3);
            int off = row * ASTRIDE + c;
            *(uint2*)(As_h + off) = make_uint2(h01, h23);
            *(uint2*)(As_l + off) = make_uint2(pack_bf2(r0, r1), pack_bf2(r2, r3));
        }
        *(uint4*)(Bs_h + soff)     = *(const uint4*)(Bh + k0);
        *(uint4*)(Bs_h + soff + 8) = *(const uint4*)(Bh + k0 + 8);
        *(uint4*)(Bs_l + soff)     = *(const uint4*)(Bl + k0);
        *(uint4*)(Bs_l + soff + 8) = *(const uint4*)(Bl + k0 + 8);
        __syncthreads();
        compute_k32(bAh, bAl, bBh, bBl, acc, wm, wn, l);
        __syncthreads();
    }
    epilogue(g_h2, DD2, m0, n0, acc, wm, wn, l);
}

// ---------------- warp-per-node gather aggregation + fused BN stats (atomic-free) ----
// grid: exactly NNODES/8 blocks of 256 threads (50000 % 8 == 0) -> every warp owns a node.
template <int DIM>
__global__ void k_aggw(const float* __restrict__ H, float* __restrict__ O,
                       float* __restrict__ gsum, float* __restrict__ gsq) {
    __shared__ float psum[8][DIM];   // per-warp slices, every slot written exactly once
    __shared__ float psq[8][DIM];
    int tid = threadIdx.x;
    int w = tid >> 5, lane = tid & 31;
    int d = blockIdx.x * 8 + w;

    constexpr int V = DIM / 128;
    float dd = g_dis[d];
    const float4* Hd = (const float4*)(H + (size_t)d * DIM);
    float4 acc[V];
#pragma unroll
    for (int v = 0; v < V; v++) {
        float4 x = Hd[lane + 32 * v];
        acc[v] = make_float4(dd * x.x, dd * x.y, dd * x.z, dd * x.w);
    }
    int beg = g_rowoff[d], end = g_rowoff[d + 1];
    for (int base = beg; base < end; base += 32) {
        int cnt = min(end - base, 32);
        int s = 0; float wgt = 0.f;
        if (lane < cnt) {
            s = g_csr[base + lane];
            wgt = g_dis[s];
        }
        for (int j = 0; j < cnt; j++) {
            int sj = __shfl_sync(0xffffffffu, s, j);
            float wj = __shfl_sync(0xffffffffu, wgt, j);
            const float4* R = (const float4*)(H + (size_t)sj * DIM);
#pragma unroll
            for (int v = 0; v < V; v++) {
                float4 x = R[lane + 32 * v];
                acc[v].x = fmaf(wj, x.x, acc[v].x);
                acc[v].y = fmaf(wj, x.y, acc[v].y);
                acc[v].z = fmaf(wj, x.z, acc[v].z);
                acc[v].w = fmaf(wj, x.w, acc[v].w);
            }
        }
    }
    float4* Od = (float4*)(O + (size_t)d * DIM);
#pragma unroll
    for (int v = 0; v < V; v++) {
        float4 r = make_float4(acc[v].x * dd, acc[v].y * dd, acc[v].z * dd, acc[v].w * dd);
        Od[lane + 32 * v] = r;
        int c = (lane + 32 * v) * 4;
        *(float4*)&psum[w][c] = r;
        *(float4*)&psq[w][c] = make_float4(r.x * r.x, r.y * r.y, r.z * r.z, r.w * r.w);
    }
    __syncthreads();
    for (int c = tid; c < DIM; c += 256) {
        float s = 0.f, q = 0.f;
#pragma unroll
        for (int ww = 0; ww < 8; ww++) { s += psum[ww][c]; q += psq[ww][c]; }
        atomicAdd(&gsum[c], s);
        atomicAdd(&gsq[c], q);
    }
}

// ---------------- BN finalize ----------------
template <int DIM>
__device__ __forceinline__ void finalize_impl(const float* __restrict__ sum,
                                              const float* __restrict__ sq,
                                              const float* __restrict__ gamma,
                                              const float* __restrict__ beta,
                                              float* __restrict__ scale,
                                              float* __restrict__ shift) {
    int t = threadIdx.x;
    float mean = sum[t] * (1.f / NNODES);
    float var = fmaxf(sq[t] * (1.f / NNODES) - mean * mean, 0.f);
    float sc = rsqrtf(var + FEPS) * gamma[t];
    scale[t] = sc;
    shift[t] = beta[t] - mean * sc;
}
__global__ void k_finalize1(const float* g, const float* b) {
    finalize_impl<DD1>(g_sum1, g_sq1, g, b, g_scale1, g_shift1);
}
__global__ void k_finalize2(const float* g, const float* b) {
    finalize_impl<DD2>(g_sum2, g_sq2, g, b, g_scale2, g_shift2);
}

// ---------------- final BN2 apply -> d_out ----------------
__global__ void k_apply(float* __restrict__ out) {
    int i = blockIdx.x * blockDim.x + threadIdx.x;
    if (i < NNODES * DD2) {
        int c = i & (DD2 - 1);
        out[i] = g_agg2[i] * g_scale2[c] + g_shift2[c];
    }
}

// ---------------- launch ----------------
extern "C" void kernel_launch(void* const* d_in, const int* in_sizes, int n_in,
                              void* d_out, int out_size) {
    const float* x      = (const float*)d_in[0];
    const int*   e      = (const int*)d_in[1];
    const float* W1     = (const float*)d_in[2];
    const float* gamma1 = (const float*)d_in[4];
    const float* beta1  = (const float*)d_in[5];
    const float* W2     = (const float*)d_in[6];
    const float* gamma2 = (const float*)d_in[8];
    const float* beta2  = (const float*)d_in[9];
    float* out = (float*)d_out;

    void *p_h1, *p_agg1, *p_h2, *p_agg2, *p_s1, *p_q1, *p_s2, *p_q2;
    cudaGetSymbolAddress(&p_h1, g_h1);
    cudaGetSymbolAddress(&p_agg1, g_agg1);
    cudaGetSymbolAddress(&p_h2, g_h2);
    cudaGetSymbolAddress(&p_agg2, g_agg2);
    cudaGetSymbolAddress(&p_s1, g_sum1);
    cudaGetSymbolAddress(&p_q1, g_sq1);
    cudaGetSymbolAddress(&p_s2, g_sum2);
    cudaGetSymbolAddress(&p_q2, g_sq2);

    cudaFuncSetAttribute(k_gemm1, cudaFuncAttributeMaxDynamicSharedMemorySize, G1_SMEM);

    const int EG = (NEDGES + 255) / 256;
    const int MB = (NNODES + 127) / 128;       // 391
    const int AGG_G = NNODES / 8;              // 6250

    k_init<<<(NNODES + 255) / 256, 256>>>(e);
    k_split_x<<<(NNODES * INDIM / 4 + 255) / 256, 256>>>(x);
    k_split_w1<<<(DD1 * INDIM + 255) / 256, 256>>>(W1);
    k_split_w2<<<(DD2 * DD1 + 255) / 256, 256>>>(W2);

    k_degree<<<EG, 256>>>(e);
    k_scan_a<<<SCANB, 256>>>();
    k_scan_b<<<1, 256>>>();
    k_scan_c<<<SCANB, 256>>>();
    k_scatter<<<EG, 256>>>(e);

    k_gemm1<<<dim3(2, MB), 256, G1_SMEM>>>();
    k_aggw<DD1><<<AGG_G, 256>>>((const float*)p_h1, (float*)p_agg1, (float*)p_s1, (float*)p_q1);
    k_finalize1<<<1, DD1>>>(gamma1, beta1);

    k_gemm2<<<dim3(1, MB), 256>>>();
    k_aggw<DD2><<<AGG_G, 256>>>((const float*)p_h2, (float*)p_agg2, (float*)p_s2, (float*)p_q2);
    k_finalize2<<<1, DD2>>>(gamma2, beta2);

    k_apply<<<(NNODES * DD2 + 255) / 256, 256>>>(out);
}

// round 11
// speedup vs baseline: 1.0708x; 1.0091x over previous
#include <cuda_runtime.h>
#include <cuda_bf16.h>
#include <math.h>
#include <stdint.h>

#define NNODES 50000
#define NEDGES 1600000
#define INDIM  512
#define DD1    256
#define DD2    128
#define FEPS   1e-5f
#define SCANB  ((NNODES + 255) / 256)   // 196

// ---------------- device scratch ----------------
__device__ int   g_is64;
__device__ int   g_deg[NNODES];
__device__ float g_dis[NNODES];
__device__ int   g_rowoff[NNODES + 1];
__device__ int   g_cursor[NNODES];
__device__ int   g_csr[NEDGES];
__device__ int   g_bsum[SCANB];
__device__ int   g_bpre[SCANB];
__device__ __nv_bfloat16 g_xh[(size_t)NNODES * INDIM];
__device__ __nv_bfloat16 g_xl[(size_t)NNODES * INDIM];
__device__ __nv_bfloat16 g_w1ht[DD1 * INDIM];   // [n][k]
__device__ __nv_bfloat16 g_w1lt[DD1 * INDIM];
__device__ __nv_bfloat16 g_w2ht[DD2 * DD1];
__device__ __nv_bfloat16 g_w2lt[DD2 * DD1];
__device__ float g_h1[(size_t)NNODES * DD1];
__device__ float g_agg1[(size_t)NNODES * DD1];
__device__ float g_h2[(size_t)NNODES * DD2];
__device__ float g_agg2[(size_t)NNODES * DD2];
__device__ float g_sum1[DD1], g_sq1[DD1], g_scale1[DD1], g_shift1[DD1];
__device__ float g_sum2[DD2], g_sq2[DD2], g_scale2[DD2], g_shift2[DD2];

// ---------------- helpers ----------------
__device__ __forceinline__ uint32_t smem_u32(const void* p) {
    uint32_t a;
    asm("{ .reg .u64 t; cvta.to.shared.u64 t, %1; cvt.u32.u64 %0, t; }" : "=r"(a) : "l"(p));
    return a;
}
__device__ __forceinline__ uint32_t pack_split(float a, float b, float& ra, float& rb) {
    __nv_bfloat16 ha = __float2bfloat16(a);
    __nv_bfloat16 hb = __float2bfloat16(b);
    ra = a - __bfloat162float(ha);
    rb = b - __bfloat162float(hb);
    return (uint32_t)__bfloat16_as_ushort(ha) | ((uint32_t)__bfloat16_as_ushort(hb) << 16);
}
__device__ __forceinline__ uint32_t pack_bf2(float a, float b) {
    return (uint32_t)__bfloat16_as_ushort(__float2bfloat16(a)) |
           ((uint32_t)__bfloat16_as_ushort(__float2bfloat16(b)) << 16);
}

#define LDSM_X4(f, addr) \
    asm volatile("ldmatrix.sync.aligned.m8n8.x4.shared.b16 {%0,%1,%2,%3}, [%4];" \
        : "=r"((f)[0]), "=r"((f)[1]), "=r"((f)[2]), "=r"((f)[3]) : "r"(addr))

#define MMA_BF16(c, a, b0, b1) \
    asm volatile("mma.sync.aligned.m16n8k16.row.col.f32.bf16.bf16.f32 " \
        "{%0,%1,%2,%3}, {%4,%5,%6,%7}, {%8,%9}, {%0,%1,%2,%3};" \
        : "+f"((c)[0]), "+f"((c)[1]), "+f"((c)[2]), "+f"((c)[3]) \
        : "r"((a)[0]), "r"((a)[1]), "r"((a)[2]), "r"((a)[3]), "r"(b0), "r"(b1))

#define ASTRIDE 40   // bf16 per smem row (80B, 16B aligned, ldsm conflict-free)

// ---------------- init (+ edge dtype detect in block 0) ----------------
__global__ void k_init(const int* __restrict__ e) {
    int i = blockIdx.x * blockDim.x + threadIdx.x;
    if (i < NNODES) g_deg[i] = 0;
    if (i < DD1) { g_sum1[i] = 0.f; g_sq1[i] = 0.f; }
    if (i < DD2) { g_sum2[i] = 0.f; g_sq2[i] = 0.f; }
    if (i == 0) g_rowoff[NNODES] = NEDGES;
    if (blockIdx.x == 0) {
        __shared__ int any;
        if (threadIdx.x == 0) any = 0;
        __syncthreads();
        for (int j = threadIdx.x; j < 1024; j += blockDim.x)
            if (e[2 * j + 1] != 0) any = 1;
        __syncthreads();
        if (threadIdx.x == 0) g_is64 = (any ? 0 : 1);
    }
}
__device__ __forceinline__ int edge_at(const int* __restrict__ e, int idx, int is64) {
    return is64 ? e[2 * (long long)idx] : e[idx];
}

// ---------------- pre-split kernels ----------------
__global__ void k_split_x(const float* __restrict__ x) {
    size_t i = (size_t)blockIdx.x * blockDim.x + threadIdx.x;
    if (i < (size_t)NNODES * INDIM / 4) {
        float4 v = ((const float4*)x)[i];
        float r0, r1, r2, r3;
        uint32_t h01 = pack_split(v.x, v.y, r0, r1);
        uint32_t h23 = pack_split(v.z, v.w, r2, r3);
        ((uint2*)g_xh)[i] = make_uint2(h01, h23);
        ((uint2*)g_xl)[i] = make_uint2(pack_bf2(r0, r1), pack_bf2(r2, r3));
    }
}
__global__ void k_split_w1(const float* __restrict__ W1) {
    int i = blockIdx.x * blockDim.x + threadIdx.x;
    if (i < DD1 * INDIM) {
        int k = i & (INDIM - 1), n = i >> 9;
        float v = W1[k * DD1 + n];
        __nv_bfloat16 h = __float2bfloat16(v);
        g_w1ht[i] = h;
        g_w1lt[i] = __float2bfloat16(v - __bfloat162float(h));
    }
}
__global__ void k_split_w2(const float* __restrict__ W2) {
    int i = blockIdx.x * blockDim.x + threadIdx.x;
    if (i < DD2 * DD1) {
        int k = i & (DD1 - 1), n = i >> 8;
        float v = W2[k * DD2 + n];
        __nv_bfloat16 h = __float2bfloat16(v);
        g_w2ht[i] = h;
        g_w2lt[i] = __float2bfloat16(v - __bfloat162float(h));
    }
}

// ---------------- degree histogram ----------------
__global__ void k_degree(const int* __restrict__ e) {
    int i = blockIdx.x * blockDim.x + threadIdx.x;
    int is64 = g_is64;
    if (i < NEDGES) atomicAdd(&g_deg[edge_at(e, NEDGES + i, is64)], 1);
}

// ---------------- hierarchical scan ----------------
__global__ void k_scan_a() {
    __shared__ int red[256];
    int t = threadIdx.x;
    int i = blockIdx.x * 256 + t;
    int d = (i < NNODES) ? g_deg[i] : 0;
    if (i < NNODES) g_dis[i] = rsqrtf((float)(d + 1));
    red[t] = d;
    __syncthreads();
    for (int off = 128; off > 0; off >>= 1) {
        if (t < off) red[t] += red[t + off];
        __syncthreads();
    }
    if (t == 0) g_bsum[blockIdx.x] = red[0];
}
__global__ void k_scan_b() {
    __shared__ int s[256];
    int t = threadIdx.x;
    int v = (t < SCANB) ? g_bsum[t] : 0;
    s[t] = v;
    __syncthreads();
    for (int off = 1; off < 256; off <<= 1) {
        int u = (t >= off) ? s[t - off] : 0;
        __syncthreads();
        s[t] += u;
        __syncthreads();
    }
    if (t < SCANB) g_bpre[t] = s[t] - v;
}
__global__ void k_scan_c() {
    __shared__ int s[256];
    int t = threadIdx.x;
    int i = blockIdx.x * 256 + t;
    int d = (i < NNODES) ? g_deg[i] : 0;
    s[t] = d;
    __syncthreads();
    for (int off = 1; off < 256; off <<= 1) {
        int u = (t >= off) ? s[t - off] : 0;
        __syncthreads();
        s[t] += u;
        __syncthreads();
    }
    if (i < NNODES) {
        int excl = s[t] - d + g_bpre[blockIdx.x];
        g_rowoff[i] = excl;
        g_cursor[i] = excl;
    }
}

// ---------------- CSR bucket scatter ----------------
__global__ void k_scatter(const int* __restrict__ e) {
    int i = blockIdx.x * blockDim.x + threadIdx.x;
    int is64 = g_is64;
    if (i < NEDGES) {
        int s = edge_at(e, i, is64);
        int d = edge_at(e, NEDGES + i, is64);
        g_csr[atomicAdd(&g_cursor[d], 1)] = s;
    }
}

// ---------------- shared mma compute/epilogue ----------------
__device__ __forceinline__ void compute_k32(uint32_t bAh, uint32_t bAl, uint32_t bBh,
                                            uint32_t bBl, float (&acc)[2][8][4],
                                            int wm, int wn, int l) {
    int a_r = (l & 7) + ((l >> 3) & 1) * 8;
    int a_c = ((l >> 4) & 1) * 8;
    int b_n = (l & 7) + ((l >> 4) & 1) * 8;
    int b_k = ((l >> 3) & 1) * 8;
#pragma unroll
    for (int kk = 0; kk < 32; kk += 16) {
        uint32_t ah[2][4], al[2][4];
#pragma unroll
        for (int mi = 0; mi < 2; mi++) {
            int r = wm * 32 + mi * 16 + a_r;
            uint32_t off = (uint32_t)(r * (ASTRIDE * 2) + (kk + a_c) * 2);
            LDSM_X4(ah[mi], bAh + off);
            LDSM_X4(al[mi], bAl + off);
        }
#pragma unroll
        for (int ng = 0; ng < 4; ng++) {
            uint32_t bh[4], bl[4];
            int nr = wn * 64 + ng * 16 + b_n;
            uint32_t off = (uint32_t)(nr * (ASTRIDE * 2) + (kk + b_k) * 2);
            LDSM_X4(bh, bBh + off);
            LDSM_X4(bl, bBl + off);
#pragma unroll
            for (int mi = 0; mi < 2; mi++) {
                MMA_BF16(acc[mi][ng * 2 + 0], ah[mi], bh[0], bh[1]);
                MMA_BF16(acc[mi][ng * 2 + 0], ah[mi], bl[0], bl[1]);
                MMA_BF16(acc[mi][ng * 2 + 0], al[mi], bh[0], bh[1]);
                MMA_BF16(acc[mi][ng * 2 + 1], ah[mi], bh[2], bh[3]);
                MMA_BF16(acc[mi][ng * 2 + 1], ah[mi], bl[2], bl[3]);
                MMA_BF16(acc[mi][ng * 2 + 1], al[mi], bh[2], bh[3]);
            }
        }
    }
}
__device__ __forceinline__ void epilogue(float* __restrict__ C, int NT, int m0, int n0,
                                         float (&acc)[2][8][4], int wm, int wn, int l) {
#pragma unroll
    for (int mi = 0; mi < 2; mi++) {
#pragma unroll
        for (int ni = 0; ni < 8; ni++) {
            int r = m0 + wm * 32 + mi * 16 + (l >> 2);
            int cc = n0 + wn * 64 + ni * 8 + (l & 3) * 2;
            if (r < NNODES)
                *(float2*)(C + (size_t)r * NT + cc) = make_float2(acc[mi][ni][0], acc[mi][ni][1]);
            if (r + 8 < NNODES)
                *(float2*)(C + (size_t)(r + 8) * NT + cc) = make_float2(acc[mi][ni][2], acc[mi][ni][3]);
        }
    }
}

// ---------------- GEMM1: static smem, register double-buffered loads ----------------
__global__ __launch_bounds__(256) void k_gemm1() {
    __shared__ __align__(16) __nv_bfloat16 As_h[128 * ASTRIDE];
    __shared__ __align__(16) __nv_bfloat16 As_l[128 * ASTRIDE];
    __shared__ __align__(16) __nv_bfloat16 Bs_h[128 * ASTRIDE];
    __shared__ __align__(16) __nv_bfloat16 Bs_l[128 * ASTRIDE];
    int tid = threadIdx.x, wid = tid >> 5, l = tid & 31;
    int m0 = blockIdx.y * 128, n0 = blockIdx.x * 128;
    int wm = wid & 3, wn = wid >> 2;
    uint32_t bAh = smem_u32(As_h), bAl = smem_u32(As_l);
    uint32_t bBh = smem_u32(Bs_h), bBl = smem_u32(Bs_l);

    int row = tid >> 1, half = (tid & 1) * 16;   // 16 bf16 per thread
    int gr = m0 + row; if (gr > NNODES - 1) gr = NNODES - 1;
    const __nv_bfloat16* Ah = g_xh + (size_t)gr * INDIM + half;
    const __nv_bfloat16* Al = g_xl + (size_t)gr * INDIM + half;
    const __nv_bfloat16* Bh = g_w1ht + (size_t)(n0 + row) * INDIM + half;
    const __nv_bfloat16* Bl = g_w1lt + (size_t)(n0 + row) * INDIM + half;
    int soff = row * ASTRIDE + half;

    float acc[2][8][4];
#pragma unroll
    for (int a = 0; a < 2; a++)
#pragma unroll
        for (int b = 0; b < 8; b++)
#pragma unroll
            for (int c = 0; c < 4; c++) acc[a][b][c] = 0.f;

    uint4 rg[8];
#define G1_LOAD(k0) do { \
        rg[0] = *(const uint4*)(Ah + (k0));     rg[1] = *(const uint4*)(Ah + (k0) + 8); \
        rg[2] = *(const uint4*)(Al + (k0));     rg[3] = *(const uint4*)(Al + (k0) + 8); \
        rg[4] = *(const uint4*)(Bh + (k0));     rg[5] = *(const uint4*)(Bh + (k0) + 8); \
        rg[6] = *(const uint4*)(Bl + (k0));     rg[7] = *(const uint4*)(Bl + (k0) + 8); \
    } while (0)
#define G1_STORE() do { \
        *(uint4*)(As_h + soff) = rg[0];  *(uint4*)(As_h + soff + 8) = rg[1]; \
        *(uint4*)(As_l + soff) = rg[2];  *(uint4*)(As_l + soff + 8) = rg[3]; \
        *(uint4*)(Bs_h + soff) = rg[4];  *(uint4*)(Bs_h + soff + 8) = rg[5]; \
        *(uint4*)(Bs_l + soff) = rg[6];  *(uint4*)(Bs_l + soff + 8) = rg[7]; \
    } while (0)

    G1_LOAD(0);
    G1_STORE();
    const int NIT = INDIM / 32;   // 16
    for (int it = 0; it < NIT; it++) {
        __syncthreads();
        if (it + 1 < NIT) G1_LOAD((it + 1) * 32);   // prefetch next tile into regs
        compute_k32(bAh, bAl, bBh, bBl, acc, wm, wn, l);
        __syncthreads();
        if (it + 1 < NIT) G1_STORE();
    }
#undef G1_LOAD
#undef G1_STORE
    epilogue(g_h1, DD1, m0, n0, acc, wm, wn, l);
}

// ---------------- GEMM2: fp32 A (agg1, BN1+ReLU fused+split) x pre-split B ----------------
__global__ __launch_bounds__(256) void k_gemm2() {
    __shared__ __align__(16) __nv_bfloat16 As_h[128 * ASTRIDE];
    __shared__ __align__(16) __nv_bfloat16 As_l[128 * ASTRIDE];
    __shared__ __align__(16) __nv_bfloat16 Bs_h[128 * ASTRIDE];
    __shared__ __align__(16) __nv_bfloat16 Bs_l[128 * ASTRIDE];
    int tid = threadIdx.x, wid = tid >> 5, l = tid & 31;
    int m0 = blockIdx.y * 128, n0 = 0;
    int wm = wid & 3, wn = wid >> 2;
    uint32_t bAh = smem_u32(As_h), bAl = smem_u32(As_l);
    uint32_t bBh = smem_u32(Bs_h), bBl = smem_u32(Bs_l);

    int row = tid >> 1;
    int half = (tid & 1) * 16;
    int gr = m0 + row; if (gr > NNODES - 1) gr = NNODES - 1;
    const float* Arow = g_agg1 + (size_t)gr * DD1;
    const __nv_bfloat16* Bh = g_w2ht + (size_t)(n0 + row) * DD1 + half;
    const __nv_bfloat16* Bl = g_w2lt + (size_t)(n0 + row) * DD1 + half;
    int soff = row * ASTRIDE + half;

    float acc[2][8][4];
#pragma unroll
    for (int a = 0; a < 2; a++)
#pragma unroll
        for (int b = 0; b < 8; b++)
#pragma unroll
            for (int c = 0; c < 4; c++) acc[a][b][c] = 0.f;

    for (int k0 = 0; k0 < DD1; k0 += 32) {
#pragma unroll
        for (int q = 0; q < 4; q++) {
            int c = half + q * 4;
            float4 v = *(const float4*)(Arow + k0 + c);
            int cc = k0 + c;
            v.x = fmaxf(fmaf(v.x, g_scale1[cc + 0], g_shift1[cc + 0]), 0.f);
            v.y = fmaxf(fmaf(v.y, g_scale1[cc + 1], g_shift1[cc + 1]), 0.f);
            v.z = fmaxf(fmaf(v.z, g_scale1[cc + 2], g_shift1[cc + 2]), 0.f);
            v.w = fmaxf(fmaf(v.w, g_scale1[cc + 3], g_shift1[cc + 3]), 0.f);
            float r0, r1, r2, r3;
            uint32_t h01 = pack_split(v.x, v.y, r0, r1);
            uint32_t h23 = pack_split(v.z, v.w, r2, r3);
            int off = row * ASTRIDE + c;
            *(uint2*)(As_h + off) = make_uint2(h01, h23);
            *(uint2*)(As_l + off) = make_uint2(pack_bf2(r0, r1), pack_bf2(r2, r3));
        }
        *(uint4*)(Bs_h + soff)     = *(const uint4*)(Bh + k0);
        *(uint4*)(Bs_h + soff + 8) = *(const uint4*)(Bh + k0 + 8);
        *(uint4*)(Bs_l + soff)     = *(const uint4*)(Bl + k0);
        *(uint4*)(Bs_l + soff + 8) = *(const uint4*)(Bl + k0 + 8);
        __syncthreads();
        compute_k32(bAh, bAl, bBh, bBl, acc, wm, wn, l);
        __syncthreads();
    }
    epilogue(g_h2, DD2, m0, n0, acc, wm, wn, l);
}

// ---------------- warp-per-node gather aggregation + fused BN stats (atomic-free) ----
// grid: exactly NNODES/8 blocks of 256 threads (50000 % 8 == 0) -> every warp owns a node.
template <int DIM>
__global__ void k_aggw(const float* __restrict__ H, float* __restrict__ O,
                       float* __restrict__ gsum, float* __restrict__ gsq) {
    __shared__ float psum[8][DIM];   // per-warp slices, every slot written exactly once
    __shared__ float psq[8][DIM];
    int tid = threadIdx.x;
    int w = tid >> 5, lane = tid & 31;
    int d = blockIdx.x * 8 + w;

    constexpr int V = DIM / 128;
    float dd = g_dis[d];
    const float4* Hd = (const float4*)(H + (size_t)d * DIM);
    float4 acc[V];
#pragma unroll
    for (int v = 0; v < V; v++) {
        float4 x = Hd[lane + 32 * v];
        acc[v] = make_float4(dd * x.x, dd * x.y, dd * x.z, dd * x.w);
    }
    int beg = g_rowoff[d], end = g_rowoff[d + 1];
    for (int base = beg; base < end; base += 32) {
        int cnt = min(end - base, 32);
        int s = 0; float wgt = 0.f;
        if (lane < cnt) {
            s = g_csr[base + lane];
            wgt = g_dis[s];
        }
        for (int j = 0; j < cnt; j++) {
            int sj = __shfl_sync(0xffffffffu, s, j);
            float wj = __shfl_sync(0xffffffffu, wgt, j);
            const float4* R = (const float4*)(H + (size_t)sj * DIM);
#pragma unroll
            for (int v = 0; v < V; v++) {
                float4 x = R[lane + 32 * v];
                acc[v].x = fmaf(wj, x.x, acc[v].x);
                acc[v].y = fmaf(wj, x.y, acc[v].y);
                acc[v].z = fmaf(wj, x.z, acc[v].z);
                acc[v].w = fmaf(wj, x.w, acc[v].w);
            }
        }
    }
    float4* Od = (float4*)(O + (size_t)d * DIM);
#pragma unroll
    for (int v = 0; v < V; v++) {
        float4 r = make_float4(acc[v].x * dd, acc[v].y * dd, acc[v].z * dd, acc[v].w * dd);
        Od[lane + 32 * v] = r;
        int c = (lane + 32 * v) * 4;
        *(float4*)&psum[w][c] = r;
        *(float4*)&psq[w][c] = make_float4(r.x * r.x, r.y * r.y, r.z * r.z, r.w * r.w);
    }
    __syncthreads();
    for (int c = tid; c < DIM; c += 256) {
        float s = 0.f, q = 0.f;
#pragma unroll
        for (int ww = 0; ww < 8; ww++) { s += psum[ww][c]; q += psq[ww][c]; }
        atomicAdd(&gsum[c], s);
        atomicAdd(&gsq[c], q);
    }
}

// ---------------- BN finalize ----------------
template <int DIM>
__device__ __forceinline__ void finalize_impl(const float* __restrict__ sum,
                                              const float* __restrict__ sq,
                                              const float* __restrict__ gamma,
                                              const float* __restrict__ beta,
                                              float* __restrict__ scale,
                                              float* __restrict__ shift) {
    int t = threadIdx.x;
    float mean = sum[t] * (1.f / NNODES);
    float var = fmaxf(sq[t] * (1.f / NNODES) - mean * mean, 0.f);
    float sc = rsqrtf(var + FEPS) * gamma[t];
    scale[t] = sc;
    shift[t] = beta[t] - mean * sc;
}
__global__ void k_finalize1(const float* g, const float* b) {
    finalize_impl<DD1>(g_sum1, g_sq1, g, b, g_scale1, g_shift1);
}
__global__ void k_finalize2(const float* g, const float* b) {
    finalize_impl<DD2>(g_sum2, g_sq2, g, b, g_scale2, g_shift2);
}

// ---------------- final BN2 apply -> d_out ----------------
__global__ void k_apply(float* __restrict__ out) {
    int i = blockIdx.x * blockDim.x + threadIdx.x;
    if (i < NNODES * DD2) {
        int c = i & (DD2 - 1);
        out[i] = g_agg2[i] * g_scale2[c] + g_shift2[c];
    }
}

// ---------------- launch ----------------
extern "C" void kernel_launch(void* const* d_in, const int* in_sizes, int n_in,
                              void* d_out, int out_size) {
    const float* x      = (const float*)d_in[0];
    const int*   e      = (const int*)d_in[1];
    const float* W1     = (const float*)d_in[2];
    const float* gamma1 = (const float*)d_in[4];
    const float* beta1  = (const float*)d_in[5];
    const float* W2     = (const float*)d_in[6];
    const float* gamma2 = (const float*)d_in[8];
    const float* beta2  = (const float*)d_in[9];
    float* out = (float*)d_out;

    void *p_h1, *p_agg1, *p_h2, *p_agg2, *p_s1, *p_q1, *p_s2, *p_q2;
    cudaGetSymbolAddress(&p_h1, g_h1);
    cudaGetSymbolAddress(&p_agg1, g_agg1);
    cudaGetSymbolAddress(&p_h2, g_h2);
    cudaGetSymbolAddress(&p_agg2, g_agg2);
    cudaGetSymbolAddress(&p_s1, g_sum1);
    cudaGetSymbolAddress(&p_q1, g_sq1);
    cudaGetSymbolAddress(&p_s2, g_sum2);
    cudaGetSymbolAddress(&p_q2, g_sq2);

    const int EG = (NEDGES + 255) / 256;
    const int MB = (NNODES + 127) / 128;       // 391
    const int AGG_G = NNODES / 8;              // 6250

    k_init<<<(NNODES + 255) / 256, 256>>>(e);
    k_split_x<<<(NNODES * INDIM / 4 + 255) / 256, 256>>>(x);
    k_split_w1<<<(DD1 * INDIM + 255) / 256, 256>>>(W1);
    k_split_w2<<<(DD2 * DD1 + 255) / 256, 256>>>(W2);

    k_degree<<<EG, 256>>>(e);
    k_scan_a<<<SCANB, 256>>>();
    k_scan_b<<<1, 256>>>();
    k_scan_c<<<SCANB, 256>>>();
    k_scatter<<<EG, 256>>>(e);

    k_gemm1<<<dim3(2, MB), 256>>>();
    k_aggw<DD1><<<AGG_G, 256>>>((const float*)p_h1, (float*)p_agg1, (float*)p_s1, (float*)p_q1);
    k_finalize1<<<1, DD1>>>(gamma1, beta1);

    k_gemm2<<<dim3(1, MB), 256>>>();
    k_aggw<DD2><<<AGG_G, 256>>>((const float*)p_h2, (float*)p_agg2, (float*)p_s2, (float*)p_q2);
    k_finalize2<<<1, DD2>>>(gamma2, beta2);

    k_apply<<<(NNODES * DD2 + 255) / 256, 256>>>(out);
}

// round 12
// speedup vs baseline: 1.1189x; 1.0449x over previous
#include <cuda_runtime.h>
#include <cuda_bf16.h>
#include <math.h>
#include <stdint.h>

#define NNODES 50000
#define NEDGES 1600000
#define INDIM  512
#define DD1    256
#define DD2    128
#define FEPS   1e-5f
#define SCANB  ((NNODES + 255) / 256)   // 196

// ---------------- device scratch ----------------
__device__ int   g_is64;
__device__ int   g_deg[NNODES];
__device__ float g_dis[NNODES];
__device__ int   g_rowoff[NNODES + 1];
__device__ int   g_cursor[NNODES];
__device__ int   g_csr[NEDGES];
__device__ int   g_bsum[SCANB];
__device__ int   g_bpre[SCANB];
__device__ __nv_bfloat16 g_xh[(size_t)NNODES * INDIM];
__device__ __nv_bfloat16 g_xl[(size_t)NNODES * INDIM];
__device__ __nv_bfloat16 g_w1ht[DD1 * INDIM];   // [n][k]
__device__ __nv_bfloat16 g_w1lt[DD1 * INDIM];
__device__ __nv_bfloat16 g_w2ht[DD2 * DD1];
__device__ __nv_bfloat16 g_w2lt[DD2 * DD1];
__device__ float g_h1[(size_t)NNODES * DD1];
__device__ float g_agg1[(size_t)NNODES * DD1];
__device__ float g_h2[(size_t)NNODES * DD2];
__device__ float g_agg2[(size_t)NNODES * DD2];
__device__ float g_sum1[DD1], g_sq1[DD1], g_scale1[DD1], g_shift1[DD1];
__device__ float g_sum2[DD2], g_sq2[DD2], g_scale2[DD2], g_shift2[DD2];

// ---------------- helpers ----------------
__device__ __forceinline__ uint32_t smem_u32(const void* p) {
    uint32_t a;
    asm("{ .reg .u64 t; cvta.to.shared.u64 t, %1; cvt.u32.u64 %0, t; }" : "=r"(a) : "l"(p));
    return a;
}
__device__ __forceinline__ uint32_t pack_split(float a, float b, float& ra, float& rb) {
    __nv_bfloat16 ha = __float2bfloat16(a);
    __nv_bfloat16 hb = __float2bfloat16(b);
    ra = a - __bfloat162float(ha);
    rb = b - __bfloat162float(hb);
    return (uint32_t)__bfloat16_as_ushort(ha) | ((uint32_t)__bfloat16_as_ushort(hb) << 16);
}
__device__ __forceinline__ uint32_t pack_bf2(float a, float b) {
    return (uint32_t)__bfloat16_as_ushort(__float2bfloat16(a)) |
           ((uint32_t)__bfloat16_as_ushort(__float2bfloat16(b)) << 16);
}

#define LDSM_X4(f, addr) \
    asm volatile("ldmatrix.sync.aligned.m8n8.x4.shared.b16 {%0,%1,%2,%3}, [%4];" \
        : "=r"((f)[0]), "=r"((f)[1]), "=r"((f)[2]), "=r"((f)[3]) : "r"(addr))

#define MMA_BF16(c, a, b0, b1) \
    asm volatile("mma.sync.aligned.m16n8k16.row.col.f32.bf16.bf16.f32 " \
        "{%0,%1,%2,%3}, {%4,%5,%6,%7}, {%8,%9}, {%0,%1,%2,%3};" \
        : "+f"((c)[0]), "+f"((c)[1]), "+f"((c)[2]), "+f"((c)[3]) \
        : "r"((a)[0]), "r"((a)[1]), "r"((a)[2]), "r"((a)[3]), "r"(b0), "r"(b1))

#define ASTRIDE 40   // bf16 per smem row (80B, 16B aligned, ldsm conflict-free)

// ---------------- init (+ edge dtype detect in block 0) ----------------
__global__ void k_init(const int* __restrict__ e) {
    int i = blockIdx.x * blockDim.x + threadIdx.x;
    if (i < NNODES) g_deg[i] = 0;
    if (i < DD1) { g_sum1[i] = 0.f; g_sq1[i] = 0.f; }
    if (i < DD2) { g_sum2[i] = 0.f; g_sq2[i] = 0.f; }
    if (i == 0) g_rowoff[NNODES] = NEDGES;
    if (blockIdx.x == 0) {
        __shared__ int any;
        if (threadIdx.x == 0) any = 0;
        __syncthreads();
        for (int j = threadIdx.x; j < 1024; j += blockDim.x)
            if (e[2 * j + 1] != 0) any = 1;
        __syncthreads();
        if (threadIdx.x == 0) g_is64 = (any ? 0 : 1);
    }
}
__device__ __forceinline__ int edge_at(const int* __restrict__ e, int idx, int is64) {
    return is64 ? e[2 * (long long)idx] : e[idx];
}

// ---------------- pre-split kernels ----------------
__global__ void k_split_x(const float* __restrict__ x) {
    size_t i = (size_t)blockIdx.x * blockDim.x + threadIdx.x;
    if (i < (size_t)NNODES * INDIM / 4) {
        float4 v = ((const float4*)x)[i];
        float r0, r1, r2, r3;
        uint32_t h01 = pack_split(v.x, v.y, r0, r1);
        uint32_t h23 = pack_split(v.z, v.w, r2, r3);
        ((uint2*)g_xh)[i] = make_uint2(h01, h23);
        ((uint2*)g_xl)[i] = make_uint2(pack_bf2(r0, r1), pack_bf2(r2, r3));
    }
}
__global__ void k_split_w1(const float* __restrict__ W1) {
    int i = blockIdx.x * blockDim.x + threadIdx.x;
    if (i < DD1 * INDIM) {
        int k = i & (INDIM - 1), n = i >> 9;
        float v = W1[k * DD1 + n];
        __nv_bfloat16 h = __float2bfloat16(v);
        g_w1ht[i] = h;
        g_w1lt[i] = __float2bfloat16(v - __bfloat162float(h));
    }
}
__global__ void k_split_w2(const float* __restrict__ W2) {
    int i = blockIdx.x * blockDim.x + threadIdx.x;
    if (i < DD2 * DD1) {
        int k = i & (DD1 - 1), n = i >> 8;
        float v = W2[k * DD2 + n];
        __nv_bfloat16 h = __float2bfloat16(v);
        g_w2ht[i] = h;
        g_w2lt[i] = __float2bfloat16(v - __bfloat162float(h));
    }
}

// ---------------- degree histogram ----------------
__global__ void k_degree(const int* __restrict__ e) {
    int i = blockIdx.x * blockDim.x + threadIdx.x;
    int is64 = g_is64;
    if (i < NEDGES) atomicAdd(&g_deg[edge_at(e, NEDGES + i, is64)], 1);
}

// ---------------- hierarchical scan ----------------
__global__ void k_scan_a() {
    __shared__ int red[256];
    int t = threadIdx.x;
    int i = blockIdx.x * 256 + t;
    int d = (i < NNODES) ? g_deg[i] : 0;
    if (i < NNODES) g_dis[i] = rsqrtf((float)(d + 1));
    red[t] = d;
    __syncthreads();
    for (int off = 128; off > 0; off >>= 1) {
        if (t < off) red[t] += red[t + off];
        __syncthreads();
    }
    if (t == 0) g_bsum[blockIdx.x] = red[0];
}
__global__ void k_scan_b() {
    __shared__ int s[256];
    int t = threadIdx.x;
    int v = (t < SCANB) ? g_bsum[t] : 0;
    s[t] = v;
    __syncthreads();
    for (int off = 1; off < 256; off <<= 1) {
        int u = (t >= off) ? s[t - off] : 0;
        __syncthreads();
        s[t] += u;
        __syncthreads();
    }
    if (t < SCANB) g_bpre[t] = s[t] - v;
}
__global__ void k_scan_c() {
    __shared__ int s[256];
    int t = threadIdx.x;
    int i = blockIdx.x * 256 + t;
    int d = (i < NNODES) ? g_deg[i] : 0;
    s[t] = d;
    __syncthreads();
    for (int off = 1; off < 256; off <<= 1) {
        int u = (t >= off) ? s[t - off] : 0;
        __syncthreads();
        s[t] += u;
        __syncthreads();
    }
    if (i < NNODES) {
        int excl = s[t] - d + g_bpre[blockIdx.x];
        g_rowoff[i] = excl;
        g_cursor[i] = excl;
    }
}

// ---------------- CSR bucket scatter ----------------
__global__ void k_scatter(const int* __restrict__ e) {
    int i = blockIdx.x * blockDim.x + threadIdx.x;
    int is64 = g_is64;
    if (i < NEDGES) {
        int s = edge_at(e, i, is64);
        int d = edge_at(e, NEDGES + i, is64);
        g_csr[atomicAdd(&g_cursor[d], 1)] = s;
    }
}

// ---------------- shared mma compute/epilogue ----------------
__device__ __forceinline__ void compute_k32(uint32_t bAh, uint32_t bAl, uint32_t bBh,
                                            uint32_t bBl, float (&acc)[2][8][4],
                                            int wm, int wn, int l) {
    int a_r = (l & 7) + ((l >> 3) & 1) * 8;
    int a_c = ((l >> 4) & 1) * 8;
    int b_n = (l & 7) + ((l >> 4) & 1) * 8;
    int b_k = ((l >> 3) & 1) * 8;
#pragma unroll
    for (int kk = 0; kk < 32; kk += 16) {
        uint32_t ah[2][4], al[2][4];
#pragma unroll
        for (int mi = 0; mi < 2; mi++) {
            int r = wm * 32 + mi * 16 + a_r;
            uint32_t off = (uint32_t)(r * (ASTRIDE * 2) + (kk + a_c) * 2);
            LDSM_X4(ah[mi], bAh + off);
            LDSM_X4(al[mi], bAl + off);
        }
#pragma unroll
        for (int ng = 0; ng < 4; ng++) {
            uint32_t bh[4], bl[4];
            int nr = wn * 64 + ng * 16 + b_n;
            uint32_t off = (uint32_t)(nr * (ASTRIDE * 2) + (kk + b_k) * 2);
            LDSM_X4(bh, bBh + off);
            LDSM_X4(bl, bBl + off);
#pragma unroll
            for (int mi = 0; mi < 2; mi++) {
                MMA_BF16(acc[mi][ng * 2 + 0], ah[mi], bh[0], bh[1]);
                MMA_BF16(acc[mi][ng * 2 + 0], ah[mi], bl[0], bl[1]);
                MMA_BF16(acc[mi][ng * 2 + 0], al[mi], bh[0], bh[1]);
                MMA_BF16(acc[mi][ng * 2 + 1], ah[mi], bh[2], bh[3]);
                MMA_BF16(acc[mi][ng * 2 + 1], ah[mi], bl[2], bl[3]);
                MMA_BF16(acc[mi][ng * 2 + 1], al[mi], bh[2], bh[3]);
            }
        }
    }
}
__device__ __forceinline__ void epilogue(float* __restrict__ C, int NT, int m0, int n0,
                                         float (&acc)[2][8][4], int wm, int wn, int l) {
#pragma unroll
    for (int mi = 0; mi < 2; mi++) {
#pragma unroll
        for (int ni = 0; ni < 8; ni++) {
            int r = m0 + wm * 32 + mi * 16 + (l >> 2);
            int cc = n0 + wn * 64 + ni * 8 + (l & 3) * 2;
            if (r < NNODES)
                *(float2*)(C + (size_t)r * NT + cc) = make_float2(acc[mi][ni][0], acc[mi][ni][1]);
            if (r + 8 < NNODES)
                *(float2*)(C + (size_t)(r + 8) * NT + cc) = make_float2(acc[mi][ni][2], acc[mi][ni][3]);
        }
    }
}

// ---------------- GEMM1: static smem, register double-buffered loads ----------------
__global__ __launch_bounds__(256) void k_gemm1() {
    __shared__ __align__(16) __nv_bfloat16 As_h[128 * ASTRIDE];
    __shared__ __align__(16) __nv_bfloat16 As_l[128 * ASTRIDE];
    __shared__ __align__(16) __nv_bfloat16 Bs_h[128 * ASTRIDE];
    __shared__ __align__(16) __nv_bfloat16 Bs_l[128 * ASTRIDE];
    int tid = threadIdx.x, wid = tid >> 5, l = tid & 31;
    int m0 = blockIdx.y * 128, n0 = blockIdx.x * 128;
    int wm = wid & 3, wn = wid >> 2;
    uint32_t bAh = smem_u32(As_h), bAl = smem_u32(As_l);
    uint32_t bBh = smem_u32(Bs_h), bBl = smem_u32(Bs_l);

    int row = tid >> 1, half = (tid & 1) * 16;   // 16 bf16 per thread
    int gr = m0 + row; if (gr > NNODES - 1) gr = NNODES - 1;
    const __nv_bfloat16* Ah = g_xh + (size_t)gr * INDIM + half;
    const __nv_bfloat16* Al = g_xl + (size_t)gr * INDIM + half;
    const __nv_bfloat16* Bh = g_w1ht + (size_t)(n0 + row) * INDIM + half;
    const __nv_bfloat16* Bl = g_w1lt + (size_t)(n0 + row) * INDIM + half;
    int soff = row * ASTRIDE + half;

    float acc[2][8][4];
#pragma unroll
    for (int a = 0; a < 2; a++)
#pragma unroll
        for (int b = 0; b < 8; b++)
#pragma unroll
            for (int c = 0; c < 4; c++) acc[a][b][c] = 0.f;

    uint4 rg[8];
#define G1_LOAD(k0) do { \
        rg[0] = *(const uint4*)(Ah + (k0));     rg[1] = *(const uint4*)(Ah + (k0) + 8); \
        rg[2] = *(const uint4*)(Al + (k0));     rg[3] = *(const uint4*)(Al + (k0) + 8); \
        rg[4] = *(const uint4*)(Bh + (k0));     rg[5] = *(const uint4*)(Bh + (k0) + 8); \
        rg[6] = *(const uint4*)(Bl + (k0));     rg[7] = *(const uint4*)(Bl + (k0) + 8); \
    } while (0)
#define G1_STORE() do { \
        *(uint4*)(As_h + soff) = rg[0];  *(uint4*)(As_h + soff + 8) = rg[1]; \
        *(uint4*)(As_l + soff) = rg[2];  *(uint4*)(As_l + soff + 8) = rg[3]; \
        *(uint4*)(Bs_h + soff) = rg[4];  *(uint4*)(Bs_h + soff + 8) = rg[5]; \
        *(uint4*)(Bs_l + soff) = rg[6];  *(uint4*)(Bs_l + soff + 8) = rg[7]; \
    } while (0)

    G1_LOAD(0);
    G1_STORE();
    const int NIT = INDIM / 32;   // 16
    for (int it = 0; it < NIT; it++) {
        __syncthreads();
        if (it + 1 < NIT) G1_LOAD((it + 1) * 32);   // prefetch next tile into regs
        compute_k32(bAh, bAl, bBh, bBl, acc, wm, wn, l);
        __syncthreads();
        if (it + 1 < NIT) G1_STORE();
    }
#undef G1_LOAD
#undef G1_STORE
    epilogue(g_h1, DD1, m0, n0, acc, wm, wn, l);
}

// ---------------- GEMM2: fp32 A (agg1, BN1+ReLU fused+split) x pre-split B ----------------
__global__ __launch_bounds__(256) void k_gemm2() {
    __shared__ __align__(16) __nv_bfloat16 As_h[128 * ASTRIDE];
    __shared__ __align__(16) __nv_bfloat16 As_l[128 * ASTRIDE];
    __shared__ __align__(16) __nv_bfloat16 Bs_h[128 * ASTRIDE];
    __shared__ __align__(16) __nv_bfloat16 Bs_l[128 * ASTRIDE];
    int tid = threadIdx.x, wid = tid >> 5, l = tid & 31;
    int m0 = blockIdx.y * 128, n0 = 0;
    int wm = wid & 3, wn = wid >> 2;
    uint32_t bAh = smem_u32(As_h), bAl = smem_u32(As_l);
    uint32_t bBh = smem_u32(Bs_h), bBl = smem_u32(Bs_l);

    int row = tid >> 1;
    int half = (tid & 1) * 16;
    int gr = m0 + row; if (gr > NNODES - 1) gr = NNODES - 1;
    const float* Arow = g_agg1 + (size_t)gr * DD1;
    const __nv_bfloat16* Bh = g_w2ht + (size_t)(n0 + row) * DD1 + half;
    const __nv_bfloat16* Bl = g_w2lt + (size_t)(n0 + row) * DD1 + half;
    int soff = row * ASTRIDE + half;

    float acc[2][8][4];
#pragma unroll
    for (int a = 0; a < 2; a++)
#pragma unroll
        for (int b = 0; b < 8; b++)
#pragma unroll
            for (int c = 0; c < 4; c++) acc[a][b][c] = 0.f;

    for (int k0 = 0; k0 < DD1; k0 += 32) {
#pragma unroll
        for (int q = 0; q < 4; q++) {
            int c = half + q * 4;
            float4 v = *(const float4*)(Arow + k0 + c);
            int cc = k0 + c;
            v.x = fmaxf(fmaf(v.x, g_scale1[cc + 0], g_shift1[cc + 0]), 0.f);
            v.y = fmaxf(fmaf(v.y, g_scale1[cc + 1], g_shift1[cc + 1]), 0.f);
            v.z = fmaxf(fmaf(v.z, g_scale1[cc + 2], g_shift1[cc + 2]), 0.f);
            v.w = fmaxf(fmaf(v.w, g_scale1[cc + 3], g_shift1[cc + 3]), 0.f);
            float r0, r1, r2, r3;
            uint32_t h01 = pack_split(v.x, v.y, r0, r1);
            uint32_t h23 = pack_split(v.z, v.w, r2, r3);
            int off = row * ASTRIDE + c;
            *(uint2*)(As_h + off) = make_uint2(h01, h23);
            *(uint2*)(As_l + off) = make_uint2(pack_bf2(r0, r1), pack_bf2(r2, r3));
        }
        *(uint4*)(Bs_h + soff)     = *(const uint4*)(Bh + k0);
        *(uint4*)(Bs_h + soff + 8) = *(const uint4*)(Bh + k0 + 8);
        *(uint4*)(Bs_l + soff)     = *(const uint4*)(Bl + k0);
        *(uint4*)(Bs_l + soff + 8) = *(const uint4*)(Bl + k0 + 8);
        __syncthreads();
        compute_k32(bAh, bAl, bBh, bBl, acc, wm, wn, l);
        __syncthreads();
    }
    epilogue(g_h2, DD2, m0, n0, acc, wm, wn, l);
}

// ---------------- warp-per-node gather aggregation + fused BN stats (atomic-free) ----
template <int DIM>
__global__ void k_aggw(const float* __restrict__ H, float* __restrict__ O,
                       float* __restrict__ gsum, float* __restrict__ gsq) {
    __shared__ float psum[8][DIM];
    __shared__ float psq[8][DIM];
    int tid = threadIdx.x;
    int w = tid >> 5, lane = tid & 31;
    int d = blockIdx.x * 8 + w;

    constexpr int V = DIM / 128;
    float dd = g_dis[d];
    const float4* Hd = (const float4*)(H + (size_t)d * DIM);
    float4 acc[V];
#pragma unroll
    for (int v = 0; v < V; v++) {
        float4 x = Hd[lane + 32 * v];
        acc[v] = make_float4(dd * x.x, dd * x.y, dd * x.z, dd * x.w);
    }
    int beg = g_rowoff[d], end = g_rowoff[d + 1];
    for (int base = beg; base < end; base += 32) {
        int cnt = min(end - base, 32);
        int s = 0; float wgt = 0.f;
        if (lane < cnt) {
            s = g_csr[base + lane];
            wgt = g_dis[s];
        }
        for (int j = 0; j < cnt; j++) {
            int sj = __shfl_sync(0xffffffffu, s, j);
            float wj = __shfl_sync(0xffffffffu, wgt, j);
            const float4* R = (const float4*)(H + (size_t)sj * DIM);
#pragma unroll
            for (int v = 0; v < V; v++) {
                float4 x = R[lane + 32 * v];
                acc[v].x = fmaf(wj, x.x, acc[v].x);
                acc[v].y = fmaf(wj, x.y, acc[v].y);
                acc[v].z = fmaf(wj, x.z, acc[v].z);
                acc[v].w = fmaf(wj, x.w, acc[v].w);
            }
        }
    }
    float4* Od = (float4*)(O + (size_t)d * DIM);
#pragma unroll
    for (int v = 0; v < V; v++) {
        float4 r = make_float4(acc[v].x * dd, acc[v].y * dd, acc[v].z * dd, acc[v].w * dd);
        Od[lane + 32 * v] = r;
        int c = (lane + 32 * v) * 4;
        *(float4*)&psum[w][c] = r;
        *(float4*)&psq[w][c] = make_float4(r.x * r.x, r.y * r.y, r.z * r.z, r.w * r.w);
    }
    __syncthreads();
    for (int c = tid; c < DIM; c += 256) {
        float s = 0.f, q = 0.f;
#pragma unroll
        for (int ww = 0; ww < 8; ww++) { s += psum[ww][c]; q += psq[ww][c]; }
        atomicAdd(&gsum[c], s);
        atomicAdd(&gsq[c], q);
    }
}

// ---------------- BN finalize ----------------
template <int DIM>
__device__ __forceinline__ void finalize_impl(const float* __restrict__ sum,
                                              const float* __restrict__ sq,
                                              const float* __restrict__ gamma,
                                              const float* __restrict__ beta,
                                              float* __restrict__ scale,
                                              float* __restrict__ shift) {
    int t = threadIdx.x;
    float mean = sum[t] * (1.f / NNODES);
    float var = fmaxf(sq[t] * (1.f / NNODES) - mean * mean, 0.f);
    float sc = rsqrtf(var + FEPS) * gamma[t];
    scale[t] = sc;
    shift[t] = beta[t] - mean * sc;
}
__global__ void k_finalize1(const float* g, const float* b) {
    finalize_impl<DD1>(g_sum1, g_sq1, g, b, g_scale1, g_shift1);
}
__global__ void k_finalize2(const float* g, const float* b) {
    finalize_impl<DD2>(g_sum2, g_sq2, g, b, g_scale2, g_shift2);
}

// ---------------- final BN2 apply -> d_out ----------------
__global__ void k_apply(float* __restrict__ out) {
    int i = blockIdx.x * blockDim.x + threadIdx.x;
    if (i < NNODES * DD2) {
        int c = i & (DD2 - 1);
        out[i] = g_agg2[i] * g_scale2[c] + g_shift2[c];
    }
}

// ---------------- launch: fork-join graph (side stream for graph build) --------
extern "C" void kernel_launch(void* const* d_in, const int* in_sizes, int n_in,
                              void* d_out, int out_size) {
    const float* x      = (const float*)d_in[0];
    const int*   e      = (const int*)d_in[1];
    const float* W1     = (const float*)d_in[2];
    const float* gamma1 = (const float*)d_in[4];
    const float* beta1  = (const float*)d_in[5];
    const float* W2     = (const float*)d_in[6];
    const float* gamma2 = (const float*)d_in[8];
    const float* beta2  = (const float*)d_in[9];
    float* out = (float*)d_out;

    void *p_h1, *p_agg1, *p_h2, *p_agg2, *p_s1, *p_q1, *p_s2, *p_q2;
    cudaGetSymbolAddress(&p_h1, g_h1);
    cudaGetSymbolAddress(&p_agg1, g_agg1);
    cudaGetSymbolAddress(&p_h2, g_h2);
    cudaGetSymbolAddress(&p_agg2, g_agg2);
    cudaGetSymbolAddress(&p_s1, g_sum1);
    cudaGetSymbolAddress(&p_q1, g_sq1);
    cudaGetSymbolAddress(&p_s2, g_sum2);
    cudaGetSymbolAddress(&p_q2, g_sq2);

    // one-time infrastructure handles (host-side; not device memory; replay-invariant)
    static cudaStream_t sB = 0;
    static cudaEvent_t  eF = 0, eJ = 0;
    if (!sB) {
        cudaStreamCreateWithFlags(&sB, cudaStreamNonBlocking);
        cudaEventCreateWithFlags(&eF, cudaEventDisableTiming);
        cudaEventCreateWithFlags(&eJ, cudaEventDisableTiming);
    }

    const int EG = (NEDGES + 255) / 256;
    const int MB = (NNODES + 127) / 128;       // 391
    const int AGG_G = NNODES / 8;              // 6250

    // fork: graph-build chain on side stream sB
    cudaEventRecord(eF, 0);
    cudaStreamWaitEvent(sB, eF, 0);
    k_init<<<(NNODES + 255) / 256, 256, 0, sB>>>(e);
    k_degree<<<EG, 256, 0, sB>>>(e);
    k_scan_a<<<SCANB, 256, 0, sB>>>();
    k_scan_b<<<1, 256, 0, sB>>>();
    k_scan_c<<<SCANB, 256, 0, sB>>>();
    k_scatter<<<EG, 256, 0, sB>>>(e);
    cudaEventRecord(eJ, sB);

    // main chain: split + gemm1 (independent of graph build)
    k_split_x<<<(NNODES * INDIM / 4 + 255) / 256, 256>>>(x);
    k_split_w1<<<(DD1 * INDIM + 255) / 256, 256>>>(W1);
    k_split_w2<<<(DD2 * DD1 + 255) / 256, 256>>>(W2);
    k_gemm1<<<dim3(2, MB), 256>>>();

    // join before aggregation
    cudaStreamWaitEvent(0, eJ, 0);
    k_aggw<DD1><<<AGG_G, 256>>>((const float*)p_h1, (float*)p_agg1, (float*)p_s1, (float*)p_q1);
    k_finalize1<<<1, DD1>>>(gamma1, beta1);

    k_gemm2<<<dim3(1, MB), 256>>>();
    k_aggw<DD2><<<AGG_G, 256>>>((const float*)p_h2, (float*)p_agg2, (float*)p_s2, (float*)p_q2);
    k_finalize2<<<1, DD2>>>(gamma2, beta2);

    k_apply<<<(NNODES * DD2 + 255) / 256, 256>>>(out);
}

// round 13
// speedup vs baseline: 1.2311x; 1.1003x over previous
#include <cuda_runtime.h>
#include <cuda_bf16.h>
#include <math.h>
#include <stdint.h>

#define NNODES 50000
#define NEDGES 1600000
#define INDIM  512
#define DD1    256
#define DD2    128
#define FEPS   1e-5f
#define SCANB  ((NNODES + 255) / 256)   // 196

// ---------------- device scratch ----------------
__device__ int   g_is64;
__device__ int   g_deg[NNODES];
__device__ float g_dis[NNODES];
__device__ int   g_rowoff[NNODES + 1];
__device__ int   g_cursor[NNODES];
__device__ int   g_csr[NEDGES];
__device__ int   g_bsum[SCANB];
__device__ int   g_bpre[SCANB];
__device__ __nv_bfloat16 g_w1ht[DD1 * INDIM];   // [n][k]
__device__ __nv_bfloat16 g_w1lt[DD1 * INDIM];
__device__ __nv_bfloat16 g_w2ht[DD2 * DD1];
__device__ __nv_bfloat16 g_w2lt[DD2 * DD1];
__device__ float g_h1[(size_t)NNODES * DD1];
__device__ float g_agg1[(size_t)NNODES * DD1];
__device__ float g_h2[(size_t)NNODES * DD2];
__device__ float g_agg2[(size_t)NNODES * DD2];
__device__ float g_sum1[DD1], g_sq1[DD1], g_scale1[DD1], g_shift1[DD1];
__device__ float g_sum2[DD2], g_sq2[DD2], g_scale2[DD2], g_shift2[DD2];

// ---------------- helpers ----------------
__device__ __forceinline__ uint32_t smem_u32(const void* p) {
    uint32_t a;
    asm("{ .reg .u64 t; cvta.to.shared.u64 t, %1; cvt.u32.u64 %0, t; }" : "=r"(a) : "l"(p));
    return a;
}
__device__ __forceinline__ uint32_t pack_split(float a, float b, float& ra, float& rb) {
    __nv_bfloat16 ha = __float2bfloat16(a);
    __nv_bfloat16 hb = __float2bfloat16(b);
    ra = a - __bfloat162float(ha);
    rb = b - __bfloat162float(hb);
    return (uint32_t)__bfloat16_as_ushort(ha) | ((uint32_t)__bfloat16_as_ushort(hb) << 16);
}
__device__ __forceinline__ uint32_t pack_bf2(float a, float b) {
    return (uint32_t)__bfloat16_as_ushort(__float2bfloat16(a)) |
           ((uint32_t)__bfloat16_as_ushort(__float2bfloat16(b)) << 16);
}

#define LDSM_X4(f, addr) \
    asm volatile("ldmatrix.sync.aligned.m8n8.x4.shared.b16 {%0,%1,%2,%3}, [%4];" \
        : "=r"((f)[0]), "=r"((f)[1]), "=r"((f)[2]), "=r"((f)[3]) : "r"(addr))

#define MMA_BF16(c, a, b0, b1) \
    asm volatile("mma.sync.aligned.m16n8k16.row.col.f32.bf16.bf16.f32 " \
        "{%0,%1,%2,%3}, {%4,%5,%6,%7}, {%8,%9}, {%0,%1,%2,%3};" \
        : "+f"((c)[0]), "+f"((c)[1]), "+f"((c)[2]), "+f"((c)[3]) \
        : "r"((a)[0]), "r"((a)[1]), "r"((a)[2]), "r"((a)[3]), "r"(b0), "r"(b1))

#define ASTRIDE 40   // bf16 per smem row (80B, 16B aligned, ldsm conflict-free)

// ---------------- init (+ edge dtype detect in block 0) ----------------
__global__ void k_init(const int* __restrict__ e) {
    int i = blockIdx.x * blockDim.x + threadIdx.x;
    if (i < NNODES) g_deg[i] = 0;
    if (i < DD1) { g_sum1[i] = 0.f; g_sq1[i] = 0.f; }
    if (i < DD2) { g_sum2[i] = 0.f; g_sq2[i] = 0.f; }
    if (i == 0) g_rowoff[NNODES] = NEDGES;
    if (blockIdx.x == 0) {
        __shared__ int any;
        if (threadIdx.x == 0) any = 0;
        __syncthreads();
        for (int j = threadIdx.x; j < 1024; j += blockDim.x)
            if (e[2 * j + 1] != 0) any = 1;
        __syncthreads();
        if (threadIdx.x == 0) g_is64 = (any ? 0 : 1);
    }
}
__device__ __forceinline__ int edge_at(const int* __restrict__ e, int idx, int is64) {
    return is64 ? e[2 * (long long)idx] : e[idx];
}

// ---------------- weight pre-split kernels ----------------
__global__ void k_split_w1(const float* __restrict__ W1) {
    int i = blockIdx.x * blockDim.x + threadIdx.x;
    if (i < DD1 * INDIM) {
        int k = i & (INDIM - 1), n = i >> 9;
        float v = W1[k * DD1 + n];
        __nv_bfloat16 h = __float2bfloat16(v);
        g_w1ht[i] = h;
        g_w1lt[i] = __float2bfloat16(v - __bfloat162float(h));
    }
}
__global__ void k_split_w2(const float* __restrict__ W2) {
    int i = blockIdx.x * blockDim.x + threadIdx.x;
    if (i < DD2 * DD1) {
        int k = i & (DD1 - 1), n = i >> 8;
        float v = W2[k * DD2 + n];
        __nv_bfloat16 h = __float2bfloat16(v);
        g_w2ht[i] = h;
        g_w2lt[i] = __float2bfloat16(v - __bfloat162float(h));
    }
}

// ---------------- degree histogram ----------------
__global__ void k_degree(const int* __restrict__ e) {
    int i = blockIdx.x * blockDim.x + threadIdx.x;
    int is64 = g_is64;
    if (i < NEDGES) atomicAdd(&g_deg[edge_at(e, NEDGES + i, is64)], 1);
}

// ---------------- hierarchical scan ----------------
__global__ void k_scan_a() {
    __shared__ int red[256];
    int t = threadIdx.x;
    int i = blockIdx.x * 256 + t;
    int d = (i < NNODES) ? g_deg[i] : 0;
    if (i < NNODES) g_dis[i] = rsqrtf((float)(d + 1));
    red[t] = d;
    __syncthreads();
    for (int off = 128; off > 0; off >>= 1) {
        if (t < off) red[t] += red[t + off];
        __syncthreads();
    }
    if (t == 0) g_bsum[blockIdx.x] = red[0];
}
__global__ void k_scan_b() {
    __shared__ int s[256];
    int t = threadIdx.x;
    int v = (t < SCANB) ? g_bsum[t] : 0;
    s[t] = v;
    __syncthreads();
    for (int off = 1; off < 256; off <<= 1) {
        int u = (t >= off) ? s[t - off] : 0;
        __syncthreads();
        s[t] += u;
        __syncthreads();
    }
    if (t < SCANB) g_bpre[t] = s[t] - v;
}
__global__ void k_scan_c() {
    __shared__ int s[256];
    int t = threadIdx.x;
    int i = blockIdx.x * 256 + t;
    int d = (i < NNODES) ? g_deg[i] : 0;
    s[t] = d;
    __syncthreads();
    for (int off = 1; off < 256; off <<= 1) {
        int u = (t >= off) ? s[t - off] : 0;
        __syncthreads();
        s[t] += u;
        __syncthreads();
    }
    if (i < NNODES) {
        int excl = s[t] - d + g_bpre[blockIdx.x];
        g_rowoff[i] = excl;
        g_cursor[i] = excl;
    }
}

// ---------------- CSR bucket scatter ----------------
__global__ void k_scatter(const int* __restrict__ e) {
    int i = blockIdx.x * blockDim.x + threadIdx.x;
    int is64 = g_is64;
    if (i < NEDGES) {
        int s = edge_at(e, i, is64);
        int d = edge_at(e, NEDGES + i, is64);
        g_csr[atomicAdd(&g_cursor[d], 1)] = s;
    }
}

// ---------------- shared mma compute/epilogue ----------------
__device__ __forceinline__ void compute_k32(uint32_t bAh, uint32_t bAl, uint32_t bBh,
                                            uint32_t bBl, float (&acc)[2][8][4],
                                            int wm, int wn, int l) {
    int a_r = (l & 7) + ((l >> 3) & 1) * 8;
    int a_c = ((l >> 4) & 1) * 8;
    int b_n = (l & 7) + ((l >> 4) & 1) * 8;
    int b_k = ((l >> 3) & 1) * 8;
#pragma unroll
    for (int kk = 0; kk < 32; kk += 16) {
        uint32_t ah[2][4], al[2][4];
#pragma unroll
        for (int mi = 0; mi < 2; mi++) {
            int r = wm * 32 + mi * 16 + a_r;
            uint32_t off = (uint32_t)(r * (ASTRIDE * 2) + (kk + a_c) * 2);
            LDSM_X4(ah[mi], bAh + off);
            LDSM_X4(al[mi], bAl + off);
        }
#pragma unroll
        for (int ng = 0; ng < 4; ng++) {
            uint32_t bh[4], bl[4];
            int nr = wn * 64 + ng * 16 + b_n;
            uint32_t off = (uint32_t)(nr * (ASTRIDE * 2) + (kk + b_k) * 2);
            LDSM_X4(bh, bBh + off);
            LDSM_X4(bl, bBl + off);
#pragma unroll
            for (int mi = 0; mi < 2; mi++) {
                MMA_BF16(acc[mi][ng * 2 + 0], ah[mi], bh[0], bh[1]);
                MMA_BF16(acc[mi][ng * 2 + 0], ah[mi], bl[0], bl[1]);
                MMA_BF16(acc[mi][ng * 2 + 0], al[mi], bh[0], bh[1]);
                MMA_BF16(acc[mi][ng * 2 + 1], ah[mi], bh[2], bh[3]);
                MMA_BF16(acc[mi][ng * 2 + 1], ah[mi], bl[2], bl[3]);
                MMA_BF16(acc[mi][ng * 2 + 1], al[mi], bh[2], bh[3]);
            }
        }
    }
}
__device__ __forceinline__ void epilogue(float* __restrict__ C, int NT, int m0, int n0,
                                         float (&acc)[2][8][4], int wm, int wn, int l) {
#pragma unroll
    for (int mi = 0; mi < 2; mi++) {
#pragma unroll
        for (int ni = 0; ni < 8; ni++) {
            int r = m0 + wm * 32 + mi * 16 + (l >> 2);
            int cc = n0 + wn * 64 + ni * 8 + (l & 3) * 2;
            if (r < NNODES)
                *(float2*)(C + (size_t)r * NT + cc) = make_float2(acc[mi][ni][0], acc[mi][ni][1]);
            if (r + 8 < NNODES)
                *(float2*)(C + (size_t)(r + 8) * NT + cc) = make_float2(acc[mi][ni][2], acc[mi][ni][3]);
        }
    }
}

// ---------------- unified GEMM: fp32 A with in-kernel split (+optional BN1+ReLU fuse) ---
// C[M,NT] tile 128x128 = A[M,KTOT] @ Wsplit; A converted fp32->bf16 hi/lo in staging.
template <bool FUSE, int KTOT, int NT>
__device__ __forceinline__ void gemm_fused(const float* __restrict__ A,
                                           const __nv_bfloat16* __restrict__ Wht,
                                           const __nv_bfloat16* __restrict__ Wlt,
                                           float* __restrict__ C) {
    __shared__ __align__(16) __nv_bfloat16 As_h[128 * ASTRIDE];
    __shared__ __align__(16) __nv_bfloat16 As_l[128 * ASTRIDE];
    __shared__ __align__(16) __nv_bfloat16 Bs_h[128 * ASTRIDE];
    __shared__ __align__(16) __nv_bfloat16 Bs_l[128 * ASTRIDE];
    int tid = threadIdx.x, wid = tid >> 5, l = tid & 31;
    int m0 = blockIdx.y * 128, n0 = blockIdx.x * 128;
    int wm = wid & 3, wn = wid >> 2;
    uint32_t bAh = smem_u32(As_h), bAl = smem_u32(As_l);
    uint32_t bBh = smem_u32(Bs_h), bBl = smem_u32(Bs_l);

    int row = tid >> 1;
    int half = (tid & 1) * 16;
    int gr = m0 + row; if (gr > NNODES - 1) gr = NNODES - 1;
    const float* Arow = A + (size_t)gr * KTOT;
    const __nv_bfloat16* Bh = Wht + (size_t)(n0 + row) * KTOT + half;
    const __nv_bfloat16* Bl = Wlt + (size_t)(n0 + row) * KTOT + half;
    int soff = row * ASTRIDE + half;

    float acc[2][8][4];
#pragma unroll
    for (int a = 0; a < 2; a++)
#pragma unroll
        for (int b = 0; b < 8; b++)
#pragma unroll
            for (int c = 0; c < 4; c++) acc[a][b][c] = 0.f;

    for (int k0 = 0; k0 < KTOT; k0 += 32) {
#pragma unroll
        for (int q = 0; q < 4; q++) {
            int c = half + q * 4;
            float4 v = *(const float4*)(Arow + k0 + c);
            if (FUSE) {
                int cc = k0 + c;
                v.x = fmaxf(fmaf(v.x, g_scale1[cc + 0], g_shift1[cc + 0]), 0.f);
                v.y = fmaxf(fmaf(v.y, g_scale1[cc + 1], g_shift1[cc + 1]), 0.f);
                v.z = fmaxf(fmaf(v.z, g_scale1[cc + 2], g_shift1[cc + 2]), 0.f);
                v.w = fmaxf(fmaf(v.w, g_scale1[cc + 3], g_shift1[cc + 3]), 0.f);
            }
            float r0, r1, r2, r3;
            uint32_t h01 = pack_split(v.x, v.y, r0, r1);
            uint32_t h23 = pack_split(v.z, v.w, r2, r3);
            int off = row * ASTRIDE + c;
            *(uint2*)(As_h + off) = make_uint2(h01, h23);
            *(uint2*)(As_l + off) = make_uint2(pack_bf2(r0, r1), pack_bf2(r2, r3));
        }
        *(uint4*)(Bs_h + soff)     = *(const uint4*)(Bh + k0);
        *(uint4*)(Bs_h + soff + 8) = *(const uint4*)(Bh + k0 + 8);
        *(uint4*)(Bs_l + soff)     = *(const uint4*)(Bl + k0);
        *(uint4*)(Bs_l + soff + 8) = *(const uint4*)(Bl + k0 + 8);
        __syncthreads();
        compute_k32(bAh, bAl, bBh, bBl, acc, wm, wn, l);
        __syncthreads();
    }
    epilogue(C, NT, m0, n0, acc, wm, wn, l);
}

__global__ __launch_bounds__(256) void k_gemm1(const float* __restrict__ x) {
    gemm_fused<false, INDIM, DD1>(x, g_w1ht, g_w1lt, g_h1);
}
__global__ __launch_bounds__(256) void k_gemm2() {
    gemm_fused<true, DD1, DD2>(g_agg1, g_w2ht, g_w2lt, g_h2);
}

// ---------------- warp-per-node gather aggregation + fused BN stats (atomic-free) ----
template <int DIM>
__global__ void k_aggw(const float* __restrict__ H, float* __restrict__ O,
                       float* __restrict__ gsum, float* __restrict__ gsq) {
    __shared__ float psum[8][DIM];
    __shared__ float psq[8][DIM];
    int tid = threadIdx.x;
    int w = tid >> 5, lane = tid & 31;
    int d = blockIdx.x * 8 + w;

    constexpr int V = DIM / 128;
    float dd = g_dis[d];
    const float4* Hd = (const float4*)(H + (size_t)d * DIM);
    float4 acc[V];
#pragma unroll
    for (int v = 0; v < V; v++) {
        float4 x = Hd[lane + 32 * v];
        acc[v] = make_float4(dd * x.x, dd * x.y, dd * x.z, dd * x.w);
    }
    int beg = g_rowoff[d], end = g_rowoff[d + 1];
    for (int base = beg; base < end; base += 32) {
        int cnt = min(end - base, 32);
        int s = 0; float wgt = 0.f;
        if (lane < cnt) {
            s = g_csr[base + lane];
            wgt = g_dis[s];
        }
        for (int j = 0; j < cnt; j++) {
            int sj = __shfl_sync(0xffffffffu, s, j);
            float wj = __shfl_sync(0xffffffffu, wgt, j);
            const float4* R = (const float4*)(H + (size_t)sj * DIM);
#pragma unroll
            for (int v = 0; v < V; v++) {
                float4 x = R[lane + 32 * v];
                acc[v].x = fmaf(wj, x.x, acc[v].x);
                acc[v].y = fmaf(wj, x.y, acc[v].y);
                acc[v].z = fmaf(wj, x.z, acc[v].z);
                acc[v].w = fmaf(wj, x.w, acc[v].w);
            }
        }
    }
    float4* Od = (float4*)(O + (size_t)d * DIM);
#pragma unroll
    for (int v = 0; v < V; v++) {
        float4 r = make_float4(acc[v].x * dd, acc[v].y * dd, acc[v].z * dd, acc[v].w * dd);
        Od[lane + 32 * v] = r;
        int c = (lane + 32 * v) * 4;
        *(float4*)&psum[w][c] = r;
        *(float4*)&psq[w][c] = make_float4(r.x * r.x, r.y * r.y, r.z * r.z, r.w * r.w);
    }
    __syncthreads();
    for (int c = tid; c < DIM; c += 256) {
        float s = 0.f, q = 0.f;
#pragma unroll
        for (int ww = 0; ww < 8; ww++) { s += psum[ww][c]; q += psq[ww][c]; }
        atomicAdd(&gsum[c], s);
        atomicAdd(&gsq[c], q);
    }
}

// ---------------- BN finalize ----------------
template <int DIM>
__device__ __forceinline__ void finalize_impl(const float* __restrict__ sum,
                                              const float* __restrict__ sq,
                                              const float* __restrict__ gamma,
                                              const float* __restrict__ beta,
                                              float* __restrict__ scale,
                                              float* __restrict__ shift) {
    int t = threadIdx.x;
    float mean = sum[t] * (1.f / NNODES);
    float var = fmaxf(sq[t] * (1.f / NNODES) - mean * mean, 0.f);
    float sc = rsqrtf(var + FEPS) * gamma[t];
    scale[t] = sc;
    shift[t] = beta[t] - mean * sc;
}
__global__ void k_finalize1(const float* g, const float* b) {
    finalize_impl<DD1>(g_sum1, g_sq1, g, b, g_scale1, g_shift1);
}
__global__ void k_finalize2(const float* g, const float* b) {
    finalize_impl<DD2>(g_sum2, g_sq2, g, b, g_scale2, g_shift2);
}

// ---------------- final BN2 apply -> d_out ----------------
__global__ void k_apply(float* __restrict__ out) {
    int i = blockIdx.x * blockDim.x + threadIdx.x;
    if (i < NNODES * DD2) {
        int c = i & (DD2 - 1);
        out[i] = g_agg2[i] * g_scale2[c] + g_shift2[c];
    }
}

// ---------------- launch: fork-join graph ----------------
extern "C" void kernel_launch(void* const* d_in, const int* in_sizes, int n_in,
                              void* d_out, int out_size) {
    const float* x      = (const float*)d_in[0];
    const int*   e      = (const int*)d_in[1];
    const float* W1     = (const float*)d_in[2];
    const float* gamma1 = (const float*)d_in[4];
    const float* beta1  = (const float*)d_in[5];
    const float* W2     = (const float*)d_in[6];
    const float* gamma2 = (const float*)d_in[8];
    const float* beta2  = (const float*)d_in[9];
    float* out = (float*)d_out;

    void *p_h1, *p_agg1, *p_h2, *p_agg2, *p_s1, *p_q1, *p_s2, *p_q2;
    cudaGetSymbolAddress(&p_h1, g_h1);
    cudaGetSymbolAddress(&p_agg1, g_agg1);
    cudaGetSymbolAddress(&p_h2, g_h2);
    cudaGetSymbolAddress(&p_agg2, g_agg2);
    cudaGetSymbolAddress(&p_s1, g_sum1);
    cudaGetSymbolAddress(&p_q1, g_sq1);
    cudaGetSymbolAddress(&p_s2, g_sum2);
    cudaGetSymbolAddress(&p_q2, g_sq2);

    static cudaStream_t sB = 0;
    static cudaEvent_t  eF = 0, eJ = 0;
    if (!sB) {
        cudaStreamCreateWithFlags(&sB, cudaStreamNonBlocking);
        cudaEventCreateWithFlags(&eF, cudaEventDisableTiming);
        cudaEventCreateWithFlags(&eJ, cudaEventDisableTiming);
    }

    const int EG = (NEDGES + 255) / 256;
    const int MB = (NNODES + 127) / 128;       // 391
    const int AGG_G = NNODES / 8;              // 6250

    // fork: graph-build chain + split_w2 on side stream sB
    cudaEventRecord(eF, 0);
    cudaStreamWaitEvent(sB, eF, 0);
    k_init<<<(NNODES + 255) / 256, 256, 0, sB>>>(e);
    k_degree<<<EG, 256, 0, sB>>>(e);
    k_scan_a<<<SCANB, 256, 0, sB>>>();
    k_scan_b<<<1, 256, 0, sB>>>();
    k_scan_c<<<SCANB, 256, 0, sB>>>();
    k_scatter<<<EG, 256, 0, sB>>>(e);
    k_split_w2<<<(DD2 * DD1 + 255) / 256, 256, 0, sB>>>(W2);
    cudaEventRecord(eJ, sB);

    // main chain: w1 split + gemm1 (x converted in-kernel, no split_x pass)
    k_split_w1<<<(DD1 * INDIM + 255) / 256, 256>>>(W1);
    k_gemm1<<<dim3(2, MB), 256>>>(x);

    // join before aggregation
    cudaStreamWaitEvent(0, eJ, 0);
    k_aggw<DD1><<<AGG_G, 256>>>((const float*)p_h1, (float*)p_agg1, (float*)p_s1, (float*)p_q1);
    k_finalize1<<<1, DD1>>>(gamma1, beta1);

    k_gemm2<<<dim3(1, MB), 256>>>();
    k_aggw<DD2><<<AGG_G, 256>>>((const float*)p_h2, (float*)p_agg2, (float*)p_s2, (float*)p_q2);
    k_finalize2<<<1, DD2>>>(gamma2, beta2);

    k_apply<<<(NNODES * DD2 + 255) / 256, 256>>>(out);
}

// round 14
// speedup vs baseline: 1.2402x; 1.0074x over previous
#include <cuda_runtime.h>
#include <cuda_bf16.h>
#include <math.h>
#include <stdint.h>

#define NNODES 50000
#define NEDGES 1600000
#define INDIM  512
#define DD1    256
#define DD2    128
#define FEPS   1e-5f
#define SCANB  ((NNODES + 255) / 256)   // 196

// ---------------- device scratch ----------------
__device__ int   g_is64;
__device__ int   g_deg[NNODES];
__device__ float g_dis[NNODES];
__device__ int   g_rowoff[NNODES + 1];
__device__ int   g_cursor[NNODES];
__device__ int   g_csr[NEDGES];
__device__ int   g_bsum[SCANB];
__device__ int   g_bpre[SCANB];
__device__ __nv_bfloat16 g_w1ht[DD1 * INDIM];   // [n][k]
__device__ __nv_bfloat16 g_w1lt[DD1 * INDIM];
__device__ __nv_bfloat16 g_w2ht[DD2 * DD1];
__device__ __nv_bfloat16 g_w2lt[DD2 * DD1];
__device__ float g_h1[(size_t)NNODES * DD1];
__device__ float g_agg1[(size_t)NNODES * DD1];
__device__ float g_h2[(size_t)NNODES * DD2];
__device__ float g_agg2[(size_t)NNODES * DD2];
__device__ float g_sum1[DD1], g_sq1[DD1];
__device__ float g_sum2[DD2], g_sq2[DD2];

// ---------------- helpers ----------------
__device__ __forceinline__ uint32_t smem_u32(const void* p) {
    uint32_t a;
    asm("{ .reg .u64 t; cvta.to.shared.u64 t, %1; cvt.u32.u64 %0, t; }" : "=r"(a) : "l"(p));
    return a;
}
__device__ __forceinline__ uint32_t pack_split(float a, float b, float& ra, float& rb) {
    __nv_bfloat16 ha = __float2bfloat16(a);
    __nv_bfloat16 hb = __float2bfloat16(b);
    ra = a - __bfloat162float(ha);
    rb = b - __bfloat162float(hb);
    return (uint32_t)__bfloat16_as_ushort(ha) | ((uint32_t)__bfloat16_as_ushort(hb) << 16);
}
__device__ __forceinline__ uint32_t pack_bf2(float a, float b) {
    return (uint32_t)__bfloat16_as_ushort(__float2bfloat16(a)) |
           ((uint32_t)__bfloat16_as_ushort(__float2bfloat16(b)) << 16);
}
// BN scale/shift from accumulated sums (same arithmetic as the old finalize kernels)
__device__ __forceinline__ void bn_coef(float sum, float sq, float gamma, float beta,
                                        float& sc, float& sh) {
    float mean = sum * (1.f / NNODES);
    float var = fmaxf(sq * (1.f / NNODES) - mean * mean, 0.f);
    sc = rsqrtf(var + FEPS) * gamma;
    sh = beta - mean * sc;
}

#define LDSM_X4(f, addr) \
    asm volatile("ldmatrix.sync.aligned.m8n8.x4.shared.b16 {%0,%1,%2,%3}, [%4];" \
        : "=r"((f)[0]), "=r"((f)[1]), "=r"((f)[2]), "=r"((f)[3]) : "r"(addr))

#define MMA_BF16(c, a, b0, b1) \
    asm volatile("mma.sync.aligned.m16n8k16.row.col.f32.bf16.bf16.f32 " \
        "{%0,%1,%2,%3}, {%4,%5,%6,%7}, {%8,%9}, {%0,%1,%2,%3};" \
        : "+f"((c)[0]), "+f"((c)[1]), "+f"((c)[2]), "+f"((c)[3]) \
        : "r"((a)[0]), "r"((a)[1]), "r"((a)[2]), "r"((a)[3]), "r"(b0), "r"(b1))

#define ASTRIDE 40   // bf16 per smem row (80B, 16B aligned, ldsm conflict-free)

// ---------------- init (+ edge dtype detect in block 0) ----------------
__global__ void k_init(const int* __restrict__ e) {
    int i = blockIdx.x * blockDim.x + threadIdx.x;
    if (i < NNODES) g_deg[i] = 0;
    if (i < DD1) { g_sum1[i] = 0.f; g_sq1[i] = 0.f; }
    if (i < DD2) { g_sum2[i] = 0.f; g_sq2[i] = 0.f; }
    if (i == 0) g_rowoff[NNODES] = NEDGES;
    if (blockIdx.x == 0) {
        __shared__ int any;
        if (threadIdx.x == 0) any = 0;
        __syncthreads();
        for (int j = threadIdx.x; j < 1024; j += blockDim.x)
            if (e[2 * j + 1] != 0) any = 1;
        __syncthreads();
        if (threadIdx.x == 0) g_is64 = (any ? 0 : 1);
    }
}
__device__ __forceinline__ int edge_at(const int* __restrict__ e, int idx, int is64) {
    return is64 ? e[2 * (long long)idx] : e[idx];
}

// ---------------- weight pre-split kernels ----------------
__global__ void k_split_w1(const float* __restrict__ W1) {
    int i = blockIdx.x * blockDim.x + threadIdx.x;
    if (i < DD1 * INDIM) {
        int k = i & (INDIM - 1), n = i >> 9;
        float v = W1[k * DD1 + n];
        __nv_bfloat16 h = __float2bfloat16(v);
        g_w1ht[i] = h;
        g_w1lt[i] = __float2bfloat16(v - __bfloat162float(h));
    }
}
__global__ void k_split_w2(const float* __restrict__ W2) {
    int i = blockIdx.x * blockDim.x + threadIdx.x;
    if (i < DD2 * DD1) {
        int k = i & (DD1 - 1), n = i >> 8;
        float v = W2[k * DD2 + n];
        __nv_bfloat16 h = __float2bfloat16(v);
        g_w2ht[i] = h;
        g_w2lt[i] = __float2bfloat16(v - __bfloat162float(h));
    }
}

// ---------------- degree histogram ----------------
__global__ void k_degree(const int* __restrict__ e) {
    int i = blockIdx.x * blockDim.x + threadIdx.x;
    int is64 = g_is64;
    if (i < NEDGES) atomicAdd(&g_deg[edge_at(e, NEDGES + i, is64)], 1);
}

// ---------------- hierarchical scan ----------------
__global__ void k_scan_a() {
    __shared__ int red[256];
    int t = threadIdx.x;
    int i = blockIdx.x * 256 + t;
    int d = (i < NNODES) ? g_deg[i] : 0;
    if (i < NNODES) g_dis[i] = rsqrtf((float)(d + 1));
    red[t] = d;
    __syncthreads();
    for (int off = 128; off > 0; off >>= 1) {
        if (t < off) red[t] += red[t + off];
        __syncthreads();
    }
    if (t == 0) g_bsum[blockIdx.x] = red[0];
}
__global__ void k_scan_b() {
    __shared__ int s[256];
    int t = threadIdx.x;
    int v = (t < SCANB) ? g_bsum[t] : 0;
    s[t] = v;
    __syncthreads();
    for (int off = 1; off < 256; off <<= 1) {
        int u = (t >= off) ? s[t - off] : 0;
        __syncthreads();
        s[t] += u;
        __syncthreads();
    }
    if (t < SCANB) g_bpre[t] = s[t] - v;
}
__global__ void k_scan_c() {
    __shared__ int s[256];
    int t = threadIdx.x;
    int i = blockIdx.x * 256 + t;
    int d = (i < NNODES) ? g_deg[i] : 0;
    s[t] = d;
    __syncthreads();
    for (int off = 1; off < 256; off <<= 1) {
        int u = (t >= off) ? s[t - off] : 0;
        __syncthreads();
        s[t] += u;
        __syncthreads();
    }
    if (i < NNODES) {
        int excl = s[t] - d + g_bpre[blockIdx.x];
        g_rowoff[i] = excl;
        g_cursor[i] = excl;
    }
}

// ---------------- CSR bucket scatter ----------------
__global__ void k_scatter(const int* __restrict__ e) {
    int i = blockIdx.x * blockDim.x + threadIdx.x;
    int is64 = g_is64;
    if (i < NEDGES) {
        int s = edge_at(e, i, is64);
        int d = edge_at(e, NEDGES + i, is64);
        g_csr[atomicAdd(&g_cursor[d], 1)] = s;
    }
}

// ---------------- shared mma compute/epilogue ----------------
__device__ __forceinline__ void compute_k32(uint32_t bAh, uint32_t bAl, uint32_t bBh,
                                            uint32_t bBl, float (&acc)[2][8][4],
                                            int wm, int wn, int l) {
    int a_r = (l & 7) + ((l >> 3) & 1) * 8;
    int a_c = ((l >> 4) & 1) * 8;
    int b_n = (l & 7) + ((l >> 4) & 1) * 8;
    int b_k = ((l >> 3) & 1) * 8;
#pragma unroll
    for (int kk = 0; kk < 32; kk += 16) {
        uint32_t ah[2][4], al[2][4];
#pragma unroll
        for (int mi = 0; mi < 2; mi++) {
            int r = wm * 32 + mi * 16 + a_r;
            uint32_t off = (uint32_t)(r * (ASTRIDE * 2) + (kk + a_c) * 2);
            LDSM_X4(ah[mi], bAh + off);
            LDSM_X4(al[mi], bAl + off);
        }
#pragma unroll
        for (int ng = 0; ng < 4; ng++) {
            uint32_t bh[4], bl[4];
            int nr = wn * 64 + ng * 16 + b_n;
            uint32_t off = (uint32_t)(nr * (ASTRIDE * 2) + (kk + b_k) * 2);
            LDSM_X4(bh, bBh + off);
            LDSM_X4(bl, bBl + off);
#pragma unroll
            for (int mi = 0; mi < 2; mi++) {
                MMA_BF16(acc[mi][ng * 2 + 0], ah[mi], bh[0], bh[1]);
                MMA_BF16(acc[mi][ng * 2 + 0], ah[mi], bl[0], bl[1]);
                MMA_BF16(acc[mi][ng * 2 + 0], al[mi], bh[0], bh[1]);
                MMA_BF16(acc[mi][ng * 2 + 1], ah[mi], bh[2], bh[3]);
                MMA_BF16(acc[mi][ng * 2 + 1], ah[mi], bl[2], bl[3]);
                MMA_BF16(acc[mi][ng * 2 + 1], al[mi], bh[2], bh[3]);
            }
        }
    }
}
__device__ __forceinline__ void epilogue(float* __restrict__ C, int NT, int m0, int n0,
                                         float (&acc)[2][8][4], int wm, int wn, int l) {
#pragma unroll
    for (int mi = 0; mi < 2; mi++) {
#pragma unroll
        for (int ni = 0; ni < 8; ni++) {
            int r = m0 + wm * 32 + mi * 16 + (l >> 2);
            int cc = n0 + wn * 64 + ni * 8 + (l & 3) * 2;
            if (r < NNODES)
                *(float2*)(C + (size_t)r * NT + cc) = make_float2(acc[mi][ni][0], acc[mi][ni][1]);
            if (r + 8 < NNODES)
                *(float2*)(C + (size_t)(r + 8) * NT + cc) = make_float2(acc[mi][ni][2], acc[mi][ni][3]);
        }
    }
}

// ---------------- unified GEMM: fp32 A with in-kernel split (+optional fused BN1+ReLU) ---
// FUSE path computes BN1 scale/shift per block from raw sums (no finalize kernel).
template <bool FUSE, int KTOT, int NT>
__device__ __forceinline__ void gemm_fused(const float* __restrict__ A,
                                           const __nv_bfloat16* __restrict__ Wht,
                                           const __nv_bfloat16* __restrict__ Wlt,
                                           float* __restrict__ C,
                                           const float* __restrict__ gamma,
                                           const float* __restrict__ beta) {
    __shared__ __align__(16) __nv_bfloat16 As_h[128 * ASTRIDE];
    __shared__ __align__(16) __nv_bfloat16 As_l[128 * ASTRIDE];
    __shared__ __align__(16) __nv_bfloat16 Bs_h[128 * ASTRIDE];
    __shared__ __align__(16) __nv_bfloat16 Bs_l[128 * ASTRIDE];
    __shared__ float sc1[FUSE ? KTOT : 1], sh1[FUSE ? KTOT : 1];
    int tid = threadIdx.x, wid = tid >> 5, l = tid & 31;
    int m0 = blockIdx.y * 128, n0 = blockIdx.x * 128;
    int wm = wid & 3, wn = wid >> 2;
    uint32_t bAh = smem_u32(As_h), bAl = smem_u32(As_l);
    uint32_t bBh = smem_u32(Bs_h), bBl = smem_u32(Bs_l);

    if (FUSE) {
        // per-block BN1 coefficient computation (KTOT == DD1 == 256 == blockDim)
        if (tid < KTOT) {
            float sc, sh;
            bn_coef(g_sum1[tid], g_sq1[tid], gamma[tid], beta[tid], sc, sh);
            sc1[tid] = sc;
            sh1[tid] = sh;
        }
        __syncthreads();
    }

    int row = tid >> 1;
    int half = (tid & 1) * 16;
    int gr = m0 + row; if (gr > NNODES - 1) gr = NNODES - 1;
    const float* Arow = A + (size_t)gr * KTOT;
    const __nv_bfloat16* Bh = Wht + (size_t)(n0 + row) * KTOT + half;
    const __nv_bfloat16* Bl = Wlt + (size_t)(n0 + row) * KTOT + half;
    int soff = row * ASTRIDE + half;

    float acc[2][8][4];
#pragma unroll
    for (int a = 0; a < 2; a++)
#pragma unroll
        for (int b = 0; b < 8; b++)
#pragma unroll
            for (int c = 0; c < 4; c++) acc[a][b][c] = 0.f;

    for (int k0 = 0; k0 < KTOT; k0 += 32) {
#pragma unroll
        for (int q = 0; q < 4; q++) {
            int c = half + q * 4;
            float4 v = *(const float4*)(Arow + k0 + c);
            if (FUSE) {
                int cc = k0 + c;
                v.x = fmaxf(fmaf(v.x, sc1[cc + 0], sh1[cc + 0]), 0.f);
                v.y = fmaxf(fmaf(v.y, sc1[cc + 1], sh1[cc + 1]), 0.f);
                v.z = fmaxf(fmaf(v.z, sc1[cc + 2], sh1[cc + 2]), 0.f);
                v.w = fmaxf(fmaf(v.w, sc1[cc + 3], sh1[cc + 3]), 0.f);
            }
            float r0, r1, r2, r3;
            uint32_t h01 = pack_split(v.x, v.y, r0, r1);
            uint32_t h23 = pack_split(v.z, v.w, r2, r3);
            int off = row * ASTRIDE + c;
            *(uint2*)(As_h + off) = make_uint2(h01, h23);
            *(uint2*)(As_l + off) = make_uint2(pack_bf2(r0, r1), pack_bf2(r2, r3));
        }
        *(uint4*)(Bs_h + soff)     = *(const uint4*)(Bh + k0);
        *(uint4*)(Bs_h + soff + 8) = *(const uint4*)(Bh + k0 + 8);
        *(uint4*)(Bs_l + soff)     = *(const uint4*)(Bl + k0);
        *(uint4*)(Bs_l + soff + 8) = *(const uint4*)(Bl + k0 + 8);
        __syncthreads();
        compute_k32(bAh, bAl, bBh, bBl, acc, wm, wn, l);
        __syncthreads();
    }
    epilogue(C, NT, m0, n0, acc, wm, wn, l);
}

__global__ __launch_bounds__(256) void k_gemm1(const float* __restrict__ x) {
    gemm_fused<false, INDIM, DD1>(x, g_w1ht, g_w1lt, g_h1, nullptr, nullptr);
}
__global__ __launch_bounds__(256) void k_gemm2(const float* __restrict__ gamma1,
                                               const float* __restrict__ beta1) {
    gemm_fused<true, DD1, DD2>(g_agg1, g_w2ht, g_w2lt, g_h2, gamma1, beta1);
}

// ---------------- warp-per-node gather aggregation + fused BN stats (atomic-free) ----
template <int DIM>
__global__ void k_aggw(const float* __restrict__ H, float* __restrict__ O,
                       float* __restrict__ gsum, float* __restrict__ gsq) {
    __shared__ float psum[8][DIM];
    __shared__ float psq[8][DIM];
    int tid = threadIdx.x;
    int w = tid >> 5, lane = tid & 31;
    int d = blockIdx.x * 8 + w;

    constexpr int V = DIM / 128;
    float dd = g_dis[d];
    const float4* Hd = (const float4*)(H + (size_t)d * DIM);
    float4 acc[V];
#pragma unroll
    for (int v = 0; v < V; v++) {
        float4 x = Hd[lane + 32 * v];
        acc[v] = make_float4(dd * x.x, dd * x.y, dd * x.z, dd * x.w);
    }
    int beg = g_rowoff[d], end = g_rowoff[d + 1];
    for (int base = beg; base < end; base += 32) {
        int cnt = min(end - base, 32);
        int s = 0; float wgt = 0.f;
        if (lane < cnt) {
            s = g_csr[base + lane];
            wgt = g_dis[s];
        }
        for (int j = 0; j < cnt; j++) {
            int sj = __shfl_sync(0xffffffffu, s, j);
            float wj = __shfl_sync(0xffffffffu, wgt, j);
            const float4* R = (const float4*)(H + (size_t)sj * DIM);
#pragma unroll
            for (int v = 0; v < V; v++) {
                float4 x = R[lane + 32 * v];
                acc[v].x = fmaf(wj, x.x, acc[v].x);
                acc[v].y = fmaf(wj, x.y, acc[v].y);
                acc[v].z = fmaf(wj, x.z, acc[v].z);
                acc[v].w = fmaf(wj, x.w, acc[v].w);
            }
        }
    }
    float4* Od = (float4*)(O + (size_t)d * DIM);
#pragma unroll
    for (int v = 0; v < V; v++) {
        float4 r = make_float4(acc[v].x * dd, acc[v].y * dd, acc[v].z * dd, acc[v].w * dd);
        Od[lane + 32 * v] = r;
        int c = (lane + 32 * v) * 4;
        *(float4*)&psum[w][c] = r;
        *(float4*)&psq[w][c] = make_float4(r.x * r.x, r.y * r.y, r.z * r.z, r.w * r.w);
    }
    __syncthreads();
    for (int c = tid; c < DIM; c += 256) {
        float s = 0.f, q = 0.f;
#pragma unroll
        for (int ww = 0; ww < 8; ww++) { s += psum[ww][c]; q += psq[ww][c]; }
        atomicAdd(&gsum[c], s);
        atomicAdd(&gsq[c], q);
    }
}

// ---------------- final: BN2 coefs per block + apply -> d_out ----------------
__global__ void k_apply(const float* __restrict__ gamma2, const float* __restrict__ beta2,
                        float* __restrict__ out) {
    __shared__ float sc2[DD2], sh2[DD2];
    int tid = threadIdx.x;
    if (tid < DD2) {
        float sc, sh;
        bn_coef(g_sum2[tid], g_sq2[tid], gamma2[tid], beta2[tid], sc, sh);
        sc2[tid] = sc;
        sh2[tid] = sh;
    }
    __syncthreads();
    int i = blockIdx.x * blockDim.x + tid;
    if (i < NNODES * DD2) {
        int c = i & (DD2 - 1);
        out[i] = g_agg2[i] * sc2[c] + sh2[c];
    }
}

// ---------------- launch: fork-join graph ----------------
extern "C" void kernel_launch(void* const* d_in, const int* in_sizes, int n_in,
                              void* d_out, int out_size) {
    const float* x      = (const float*)d_in[0];
    const int*   e      = (const int*)d_in[1];
    const float* W1     = (const float*)d_in[2];
    const float* gamma1 = (const float*)d_in[4];
    const float* beta1  = (const float*)d_in[5];
    const float* W2     = (const float*)d_in[6];
    const float* gamma2 = (const float*)d_in[8];
    const float* beta2  = (const float*)d_in[9];
    float* out = (float*)d_out;

    void *p_h1, *p_agg1, *p_h2, *p_agg2, *p_s1, *p_q1, *p_s2, *p_q2;
    cudaGetSymbolAddress(&p_h1, g_h1);
    cudaGetSymbolAddress(&p_agg1, g_agg1);
    cudaGetSymbolAddress(&p_h2, g_h2);
    cudaGetSymbolAddress(&p_agg2, g_agg2);
    cudaGetSymbolAddress(&p_s1, g_sum1);
    cudaGetSymbolAddress(&p_q1, g_sq1);
    cudaGetSymbolAddress(&p_s2, g_sum2);
    cudaGetSymbolAddress(&p_q2, g_sq2);

    static cudaStream_t sB = 0;
    static cudaEvent_t  eF = 0, eJ = 0;
    if (!sB) {
        cudaStreamCreateWithFlags(&sB, cudaStreamNonBlocking);
        cudaEventCreateWithFlags(&eF, cudaEventDisableTiming);
        cudaEventCreateWithFlags(&eJ, cudaEventDisableTiming);
    }

    const int EG = (NEDGES + 255) / 256;
    const int MB = (NNODES + 127) / 128;       // 391
    const int AGG_G = NNODES / 8;              // 6250

    // fork: graph-build chain + split_w2 on side stream sB
    cudaEventRecord(eF, 0);
    cudaStreamWaitEvent(sB, eF, 0);
    k_init<<<(NNODES + 255) / 256, 256, 0, sB>>>(e);
    k_degree<<<EG, 256, 0, sB>>>(e);
    k_scan_a<<<SCANB, 256, 0, sB>>>();
    k_scan_b<<<1, 256, 0, sB>>>();
    k_scan_c<<<SCANB, 256, 0, sB>>>();
    k_scatter<<<EG, 256, 0, sB>>>(e);
    k_split_w2<<<(DD2 * DD1 + 255) / 256, 256, 0, sB>>>(W2);
    cudaEventRecord(eJ, sB);

    // main chain: w1 split + gemm1 (x converted in-kernel)
    k_split_w1<<<(DD1 * INDIM + 255) / 256, 256>>>(W1);
    k_gemm1<<<dim3(2, MB), 256>>>(x);

    // join before aggregation
    cudaStreamWaitEvent(0, eJ, 0);
    k_aggw<DD1><<<AGG_G, 256>>>((const float*)p_h1, (float*)p_agg1, (float*)p_s1, (float*)p_q1);

    k_gemm2<<<dim3(1, MB), 256>>>(gamma1, beta1);
    k_aggw<DD2><<<AGG_G, 256>>>((const float*)p_h2, (float*)p_agg2, (float*)p_s2, (float*)p_q2);

    k_apply<<<(NNODES * DD2 + 255) / 256, 256>>>(gamma2, beta2, out);
}

// round 15
// speedup vs baseline: 1.3068x; 1.0537x over previous
#include <cuda_runtime.h>
#include <cuda_bf16.h>
#include <cuda_fp16.h>
#include <math.h>
#include <stdint.h>

#define NNODES 50000
#define NEDGES 1600000
#define INDIM  512
#define DD1    256
#define DD2    128
#define FEPS   1e-5f
#define SCANB  ((NNODES + 255) / 256)   // 196

// ---------------- device scratch ----------------
__device__ int   g_is64;
__device__ int   g_deg[NNODES];
__device__ float g_dis[NNODES];
__device__ int   g_rowoff[NNODES + 1];
__device__ int   g_cursor[NNODES];
__device__ int   g_csr[NEDGES];
__device__ int   g_bsum[SCANB];
__device__ int   g_bpre[SCANB];
__device__ __nv_bfloat16 g_w1ht[DD1 * INDIM];   // [n][k]
__device__ __nv_bfloat16 g_w1lt[DD1 * INDIM];
__device__ __nv_bfloat16 g_w2ht[DD2 * DD1];
__device__ __nv_bfloat16 g_w2lt[DD2 * DD1];
__device__ __half g_h1[(size_t)NNODES * DD1];   // fp16 intermediates (gather-only consumers)
__device__ __half g_h2[(size_t)NNODES * DD2];
__device__ float g_agg1[(size_t)NNODES * DD1];
__device__ float g_agg2[(size_t)NNODES * DD2];
__device__ float g_sum1[DD1], g_sq1[DD1];
__device__ float g_sum2[DD2], g_sq2[DD2];

// ---------------- helpers ----------------
__device__ __forceinline__ uint32_t smem_u32(const void* p) {
    uint32_t a;
    asm("{ .reg .u64 t; cvta.to.shared.u64 t, %1; cvt.u32.u64 %0, t; }" : "=r"(a) : "l"(p));
    return a;
}
__device__ __forceinline__ uint32_t pack_split(float a, float b, float& ra, float& rb) {
    __nv_bfloat16 ha = __float2bfloat16(a);
    __nv_bfloat16 hb = __float2bfloat16(b);
    ra = a - __bfloat162float(ha);
    rb = b - __bfloat162float(hb);
    return (uint32_t)__bfloat16_as_ushort(ha) | ((uint32_t)__bfloat16_as_ushort(hb) << 16);
}
__device__ __forceinline__ uint32_t pack_bf2(float a, float b) {
    return (uint32_t)__bfloat16_as_ushort(__float2bfloat16(a)) |
           ((uint32_t)__bfloat16_as_ushort(__float2bfloat16(b)) << 16);
}
__device__ __forceinline__ void bn_coef(float sum, float sq, float gamma, float beta,
                                        float& sc, float& sh) {
    float mean = sum * (1.f / NNODES);
    float var = fmaxf(sq * (1.f / NNODES) - mean * mean, 0.f);
    sc = rsqrtf(var + FEPS) * gamma;
    sh = beta - mean * sc;
}

#define LDSM_X4(f, addr) \
    asm volatile("ldmatrix.sync.aligned.m8n8.x4.shared.b16 {%0,%1,%2,%3}, [%4];" \
        : "=r"((f)[0]), "=r"((f)[1]), "=r"((f)[2]), "=r"((f)[3]) : "r"(addr))

#define MMA_BF16(c, a, b0, b1) \
    asm volatile("mma.sync.aligned.m16n8k16.row.col.f32.bf16.bf16.f32 " \
        "{%0,%1,%2,%3}, {%4,%5,%6,%7}, {%8,%9}, {%0,%1,%2,%3};" \
        : "+f"((c)[0]), "+f"((c)[1]), "+f"((c)[2]), "+f"((c)[3]) \
        : "r"((a)[0]), "r"((a)[1]), "r"((a)[2]), "r"((a)[3]), "r"(b0), "r"(b1))

#define ASTRIDE 40   // bf16 per smem row (80B, 16B aligned, ldsm conflict-free)

// ---------------- init (+ edge dtype detect in block 0) ----------------
__global__ void k_init(const int* __restrict__ e) {
    int i = blockIdx.x * blockDim.x + threadIdx.x;
    if (i < NNODES) g_deg[i] = 0;
    if (i < DD1) { g_sum1[i] = 0.f; g_sq1[i] = 0.f; }
    if (i < DD2) { g_sum2[i] = 0.f; g_sq2[i] = 0.f; }
    if (i == 0) g_rowoff[NNODES] = NEDGES;
    if (blockIdx.x == 0) {
        __shared__ int any;
        if (threadIdx.x == 0) any = 0;
        __syncthreads();
        for (int j = threadIdx.x; j < 1024; j += blockDim.x)
            if (e[2 * j + 1] != 0) any = 1;
        __syncthreads();
        if (threadIdx.x == 0) g_is64 = (any ? 0 : 1);
    }
}
__device__ __forceinline__ int edge_at(const int* __restrict__ e, int idx, int is64) {
    return is64 ? e[2 * (long long)idx] : e[idx];
}

// ---------------- weight pre-split kernels ----------------
__global__ void k_split_w1(const float* __restrict__ W1) {
    int i = blockIdx.x * blockDim.x + threadIdx.x;
    if (i < DD1 * INDIM) {
        int k = i & (INDIM - 1), n = i >> 9;
        float v = W1[k * DD1 + n];
        __nv_bfloat16 h = __float2bfloat16(v);
        g_w1ht[i] = h;
        g_w1lt[i] = __float2bfloat16(v - __bfloat162float(h));
    }
}
__global__ void k_split_w2(const float* __restrict__ W2) {
    int i = blockIdx.x * blockDim.x + threadIdx.x;
    if (i < DD2 * DD1) {
        int k = i & (DD1 - 1), n = i >> 8;
        float v = W2[k * DD2 + n];
        __nv_bfloat16 h = __float2bfloat16(v);
        g_w2ht[i] = h;
        g_w2lt[i] = __float2bfloat16(v - __bfloat162float(h));
    }
}

// ---------------- degree histogram ----------------
__global__ void k_degree(const int* __restrict__ e) {
    int i = blockIdx.x * blockDim.x + threadIdx.x;
    int is64 = g_is64;
    if (i < NEDGES) atomicAdd(&g_deg[edge_at(e, NEDGES + i, is64)], 1);
}

// ---------------- hierarchical scan ----------------
__global__ void k_scan_a() {
    __shared__ int red[256];
    int t = threadIdx.x;
    int i = blockIdx.x * 256 + t;
    int d = (i < NNODES) ? g_deg[i] : 0;
    if (i < NNODES) g_dis[i] = rsqrtf((float)(d + 1));
    red[t] = d;
    __syncthreads();
    for (int off = 128; off > 0; off >>= 1) {
        if (t < off) red[t] += red[t + off];
        __syncthreads();
    }
    if (t == 0) g_bsum[blockIdx.x] = red[0];
}
__global__ void k_scan_b() {
    __shared__ int s[256];
    int t = threadIdx.x;
    int v = (t < SCANB) ? g_bsum[t] : 0;
    s[t] = v;
    __syncthreads();
    for (int off = 1; off < 256; off <<= 1) {
        int u = (t >= off) ? s[t - off] : 0;
        __syncthreads();
        s[t] += u;
        __syncthreads();
    }
    if (t < SCANB) g_bpre[t] = s[t] - v;
}
__global__ void k_scan_c() {
    __shared__ int s[256];
    int t = threadIdx.x;
    int i = blockIdx.x * 256 + t;
    int d = (i < NNODES) ? g_deg[i] : 0;
    s[t] = d;
    __syncthreads();
    for (int off = 1; off < 256; off <<= 1) {
        int u = (t >= off) ? s[t - off] : 0;
        __syncthreads();
        s[t] += u;
        __syncthreads();
    }
    if (i < NNODES) {
        int excl = s[t] - d + g_bpre[blockIdx.x];
        g_rowoff[i] = excl;
        g_cursor[i] = excl;
    }
}

// ---------------- CSR bucket scatter ----------------
__global__ void k_scatter(const int* __restrict__ e) {
    int i = blockIdx.x * blockDim.x + threadIdx.x;
    int is64 = g_is64;
    if (i < NEDGES) {
        int s = edge_at(e, i, is64);
        int d = edge_at(e, NEDGES + i, is64);
        g_csr[atomicAdd(&g_cursor[d], 1)] = s;
    }
}

// ---------------- shared mma compute ----------------
__device__ __forceinline__ void compute_k32(uint32_t bAh, uint32_t bAl, uint32_t bBh,
                                            uint32_t bBl, float (&acc)[2][8][4],
                                            int wm, int wn, int l) {
    int a_r = (l & 7) + ((l >> 3) & 1) * 8;
    int a_c = ((l >> 4) & 1) * 8;
    int b_n = (l & 7) + ((l >> 4) & 1) * 8;
    int b_k = ((l >> 3) & 1) * 8;
#pragma unroll
    for (int kk = 0; kk < 32; kk += 16) {
        uint32_t ah[2][4], al[2][4];
#pragma unroll
        for (int mi = 0; mi < 2; mi++) {
            int r = wm * 32 + mi * 16 + a_r;
            uint32_t off = (uint32_t)(r * (ASTRIDE * 2) + (kk + a_c) * 2);
            LDSM_X4(ah[mi], bAh + off);
            LDSM_X4(al[mi], bAl + off);
        }
#pragma unroll
        for (int ng = 0; ng < 4; ng++) {
            uint32_t bh[4], bl[4];
            int nr = wn * 64 + ng * 16 + b_n;
            uint32_t off = (uint32_t)(nr * (ASTRIDE * 2) + (kk + b_k) * 2);
            LDSM_X4(bh, bBh + off);
            LDSM_X4(bl, bBl + off);
#pragma unroll
            for (int mi = 0; mi < 2; mi++) {
                MMA_BF16(acc[mi][ng * 2 + 0], ah[mi], bh[0], bh[1]);
                MMA_BF16(acc[mi][ng * 2 + 0], ah[mi], bl[0], bl[1]);
                MMA_BF16(acc[mi][ng * 2 + 0], al[mi], bh[0], bh[1]);
                MMA_BF16(acc[mi][ng * 2 + 1], ah[mi], bh[2], bh[3]);
                MMA_BF16(acc[mi][ng * 2 + 1], ah[mi], bl[2], bl[3]);
                MMA_BF16(acc[mi][ng * 2 + 1], al[mi], bh[2], bh[3]);
            }
        }
    }
}
// epilogue -> fp16 output (half2 stores)
__device__ __forceinline__ void epilogue_h(__half* __restrict__ C, int NT, int m0, int n0,
                                           float (&acc)[2][8][4], int wm, int wn, int l) {
#pragma unroll
    for (int mi = 0; mi < 2; mi++) {
#pragma unroll
        for (int ni = 0; ni < 8; ni++) {
            int r = m0 + wm * 32 + mi * 16 + (l >> 2);
            int cc = n0 + wn * 64 + ni * 8 + (l & 3) * 2;
            if (r < NNODES)
                *(__half2*)(C + (size_t)r * NT + cc) =
                    __floats2half2_rn(acc[mi][ni][0], acc[mi][ni][1]);
            if (r + 8 < NNODES)
                *(__half2*)(C + (size_t)(r + 8) * NT + cc) =
                    __floats2half2_rn(acc[mi][ni][2], acc[mi][ni][3]);
        }
    }
}

// ---------------- unified GEMM: fp32 A, in-kernel split (+optional fused BN1+ReLU) ---
template <bool FUSE, int KTOT, int NT>
__device__ __forceinline__ void gemm_fused(const float* __restrict__ A,
                                           const __nv_bfloat16* __restrict__ Wht,
                                           const __nv_bfloat16* __restrict__ Wlt,
                                           __half* __restrict__ C,
                                           const float* __restrict__ gamma,
                                           const float* __restrict__ beta) {
    __shared__ __align__(16) __nv_bfloat16 As_h[128 * ASTRIDE];
    __shared__ __align__(16) __nv_bfloat16 As_l[128 * ASTRIDE];
    __shared__ __align__(16) __nv_bfloat16 Bs_h[128 * ASTRIDE];
    __shared__ __align__(16) __nv_bfloat16 Bs_l[128 * ASTRIDE];
    __shared__ float sc1[FUSE ? KTOT : 1], sh1[FUSE ? KTOT : 1];
    int tid = threadIdx.x, wid = tid >> 5, l = tid & 31;
    int m0 = blockIdx.y * 128, n0 = blockIdx.x * 128;
    int wm = wid & 3, wn = wid >> 2;
    uint32_t bAh = smem_u32(As_h), bAl = smem_u32(As_l);
    uint32_t bBh = smem_u32(Bs_h), bBl = smem_u32(Bs_l);

    if (FUSE) {
        if (tid < KTOT) {
            float sc, sh;
            bn_coef(g_sum1[tid], g_sq1[tid], gamma[tid], beta[tid], sc, sh);
            sc1[tid] = sc;
            sh1[tid] = sh;
        }
        __syncthreads();
    }

    int row = tid >> 1;
    int half = (tid & 1) * 16;
    int gr = m0 + row; if (gr > NNODES - 1) gr = NNODES - 1;
    const float* Arow = A + (size_t)gr * KTOT;
    const __nv_bfloat16* Bh = Wht + (size_t)(n0 + row) * KTOT + half;
    const __nv_bfloat16* Bl = Wlt + (size_t)(n0 + row) * KTOT + half;
    int soff = row * ASTRIDE + half;

    float acc[2][8][4];
#pragma unroll
    for (int a = 0; a < 2; a++)
#pragma unroll
        for (int b = 0; b < 8; b++)
#pragma unroll
            for (int c = 0; c < 4; c++) acc[a][b][c] = 0.f;

    for (int k0 = 0; k0 < KTOT; k0 += 32) {
#pragma unroll
        for (int q = 0; q < 4; q++) {
            int c = half + q * 4;
            float4 v = *(const float4*)(Arow + k0 + c);
            if (FUSE) {
                int cc = k0 + c;
                v.x = fmaxf(fmaf(v.x, sc1[cc + 0], sh1[cc + 0]), 0.f);
                v.y = fmaxf(fmaf(v.y, sc1[cc + 1], sh1[cc + 1]), 0.f);
                v.z = fmaxf(fmaf(v.z, sc1[cc + 2], sh1[cc + 2]), 0.f);
                v.w = fmaxf(fmaf(v.w, sc1[cc + 3], sh1[cc + 3]), 0.f);
            }
            float r0, r1, r2, r3;
            uint32_t h01 = pack_split(v.x, v.y, r0, r1);
            uint32_t h23 = pack_split(v.z, v.w, r2, r3);
            int off = row * ASTRIDE + c;
            *(uint2*)(As_h + off) = make_uint2(h01, h23);
            *(uint2*)(As_l + off) = make_uint2(pack_bf2(r0, r1), pack_bf2(r2, r3));
        }
        *(uint4*)(Bs_h + soff)     = *(const uint4*)(Bh + k0);
        *(uint4*)(Bs_h + soff + 8) = *(const uint4*)(Bh + k0 + 8);
        *(uint4*)(Bs_l + soff)     = *(const uint4*)(Bl + k0);
        *(uint4*)(Bs_l + soff + 8) = *(const uint4*)(Bl + k0 + 8);
        __syncthreads();
        compute_k32(bAh, bAl, bBh, bBl, acc, wm, wn, l);
        __syncthreads();
    }
    epilogue_h(C, NT, m0, n0, acc, wm, wn, l);
}

__global__ __launch_bounds__(256) void k_gemm1(const float* __restrict__ x) {
    gemm_fused<false, INDIM, DD1>(x, g_w1ht, g_w1lt, g_h1, nullptr, nullptr);
}
__global__ __launch_bounds__(256) void k_gemm2(const float* __restrict__ gamma1,
                                               const float* __restrict__ beta1) {
    gemm_fused<true, DD1, DD2>(g_agg1, g_w2ht, g_w2lt, g_h2, gamma1, beta1);
}

// ---------------- warp-per-node fp16 gather aggregation + fused BN stats ----------
// H is fp16; accumulation and output fp32. grid = NNODES/8 blocks x 256.
template <int DIM>
__global__ void k_aggw(const __half* __restrict__ H, float* __restrict__ O,
                       float* __restrict__ gsum, float* __restrict__ gsq) {
    __shared__ float psum[8][DIM];
    __shared__ float psq[8][DIM];
    int tid = threadIdx.x;
    int w = tid >> 5, lane = tid & 31;
    int d = blockIdx.x * 8 + w;

    constexpr int V = DIM / 128;   // uint2 (4 halves) per lane per V
    float dd = g_dis[d];
    const uint2* Hd = (const uint2*)(H + (size_t)d * DIM);
    float4 acc[V];
#pragma unroll
    for (int v = 0; v < V; v++) {
        uint2 u = Hd[lane + 32 * v];
        float2 f0 = __half22float2(*(__half2*)&u.x);
        float2 f1 = __half22float2(*(__half2*)&u.y);
        acc[v] = make_float4(dd * f0.x, dd * f0.y, dd * f1.x, dd * f1.y);
    }
    int beg = g_rowoff[d], end = g_rowoff[d + 1];
    for (int base = beg; base < end; base += 32) {
        int cnt = min(end - base, 32);
        int s = 0; float wgt = 0.f;
        if (lane < cnt) {
            s = g_csr[base + lane];
            wgt = g_dis[s];
        }
        for (int j = 0; j < cnt; j++) {
            int sj = __shfl_sync(0xffffffffu, s, j);
            float wj = __shfl_sync(0xffffffffu, wgt, j);
            const uint2* R = (const uint2*)(H + (size_t)sj * DIM);
#pragma unroll
            for (int v = 0; v < V; v++) {
                uint2 u = R[lane + 32 * v];
                float2 f0 = __half22float2(*(__half2*)&u.x);
                float2 f1 = __half22float2(*(__half2*)&u.y);
                acc[v].x = fmaf(wj, f0.x, acc[v].x);
                acc[v].y = fmaf(wj, f0.y, acc[v].y);
                acc[v].z = fmaf(wj, f1.x, acc[v].z);
                acc[v].w = fmaf(wj, f1.y, acc[v].w);
            }
        }
    }
    float4* Od = (float4*)(O + (size_t)d * DIM);
#pragma unroll
    for (int v = 0; v < V; v++) {
        float4 r = make_float4(acc[v].x * dd, acc[v].y * dd, acc[v].z * dd, acc[v].w * dd);
        Od[lane + 32 * v] = r;
        int c = (lane + 32 * v) * 4;
        *(float4*)&psum[w][c] = r;
        *(float4*)&psq[w][c] = make_float4(r.x * r.x, r.y * r.y, r.z * r.z, r.w * r.w);
    }
    __syncthreads();
    for (int c = tid; c < DIM; c += 256) {
        float s = 0.f, q = 0.f;
#pragma unroll
        for (int ww = 0; ww < 8; ww++) { s += psum[ww][c]; q += psq[ww][c]; }
        atomicAdd(&gsum[c], s);
        atomicAdd(&gsq[c], q);
    }
}

// ---------------- final: BN2 coefs per block + apply -> d_out ----------------
__global__ void k_apply(const float* __restrict__ gamma2, const float* __restrict__ beta2,
                        float* __restrict__ out) {
    __shared__ float sc2[DD2], sh2[DD2];
    int tid = threadIdx.x;
    if (tid < DD2) {
        float sc, sh;
        bn_coef(g_sum2[tid], g_sq2[tid], gamma2[tid], beta2[tid], sc, sh);
        sc2[tid] = sc;
        sh2[tid] = sh;
    }
    __syncthreads();
    int i = blockIdx.x * blockDim.x + tid;
    if (i < NNODES * DD2) {
        int c = i & (DD2 - 1);
        out[i] = g_agg2[i] * sc2[c] + sh2[c];
    }
}

// ---------------- launch: fork-join graph ----------------
extern "C" void kernel_launch(void* const* d_in, const int* in_sizes, int n_in,
                              void* d_out, int out_size) {
    const float* x      = (const float*)d_in[0];
    const int*   e      = (const int*)d_in[1];
    const float* W1     = (const float*)d_in[2];
    const float* gamma1 = (const float*)d_in[4];
    const float* beta1  = (const float*)d_in[5];
    const float* W2     = (const float*)d_in[6];
    const float* gamma2 = (const float*)d_in[8];
    const float* beta2  = (const float*)d_in[9];
    float* out = (float*)d_out;

    void *p_h1, *p_agg1, *p_h2, *p_agg2, *p_s1, *p_q1, *p_s2, *p_q2;
    cudaGetSymbolAddress(&p_h1, g_h1);
    cudaGetSymbolAddress(&p_agg1, g_agg1);
    cudaGetSymbolAddress(&p_h2, g_h2);
    cudaGetSymbolAddress(&p_agg2, g_agg2);
    cudaGetSymbolAddress(&p_s1, g_sum1);
    cudaGetSymbolAddress(&p_q1, g_sq1);
    cudaGetSymbolAddress(&p_s2, g_sum2);
    cudaGetSymbolAddress(&p_q2, g_sq2);

    static cudaStream_t sB = 0;
    static cudaEvent_t  eF = 0, eJ = 0;
    if (!sB) {
        cudaStreamCreateWithFlags(&sB, cudaStreamNonBlocking);
        cudaEventCreateWithFlags(&eF, cudaEventDisableTiming);
        cudaEventCreateWithFlags(&eJ, cudaEventDisableTiming);
    }

    const int EG = (NEDGES + 255) / 256;
    const int MB = (NNODES + 127) / 128;       // 391
    const int AGG_G = NNODES / 8;              // 6250

    // fork: graph-build chain + split_w2 on side stream sB
    cudaEventRecord(eF, 0);
    cudaStreamWaitEvent(sB, eF, 0);
    k_init<<<(NNODES + 255) / 256, 256, 0, sB>>>(e);
    k_degree<<<EG, 256, 0, sB>>>(e);
    k_scan_a<<<SCANB, 256, 0, sB>>>();
    k_scan_b<<<1, 256, 0, sB>>>();
    k_scan_c<<<SCANB, 256, 0, sB>>>();
    k_scatter<<<EG, 256, 0, sB>>>(e);
    k_split_w2<<<(DD2 * DD1 + 255) / 256, 256, 0, sB>>>(W2);
    cudaEventRecord(eJ, sB);

    // main chain: w1 split + gemm1 (x converted in-kernel)
    k_split_w1<<<(DD1 * INDIM + 255) / 256, 256>>>(W1);
    k_gemm1<<<dim3(2, MB), 256>>>(x);

    // join before aggregation
    cudaStreamWaitEvent(0, eJ, 0);
    k_aggw<DD1><<<AGG_G, 256>>>((const __half*)p_h1, (float*)p_agg1, (float*)p_s1, (float*)p_q1);

    k_gemm2<<<dim3(1, MB), 256>>>(gamma1, beta1);
    k_aggw<DD2><<<AGG_G, 256>>>((const __half*)p_h2, (float*)p_agg2, (float*)p_s2, (float*)p_q2);

    k_apply<<<(NNODES * DD2 + 255) / 256, 256>>>(gamma2, beta2, out);
}